// round 3
// baseline (speedup 1.0000x reference)
#include <cuda_runtime.h>
#include <math.h>

typedef unsigned long long ull;

#define NB 64
#define NH 256
#define NG 768
#define NP 32
#define TSEQ 64
#define TDEC 54

// -------- scratch (device globals; no allocation in kernel_launch) --------
__device__ float g_gi[84934656];   // [P=32][t=54][b=64][j=768] decoder input-proj (incl b_ih)
__device__ float g_z[NB * NH];     // latent z
__device__ float g_henc[NB * NH];  // encoder final hidden

// -------- f32x2 helpers --------
__device__ __forceinline__ ull pk(float x, float y) {
    ull r; asm("mov.b64 %0, {%1,%2};" : "=l"(r) : "f"(x), "f"(y)); return r;
}
__device__ __forceinline__ ull pk2(float x) { return pk(x, x); }
__device__ __forceinline__ void upk(ull v, float& x, float& y) {
    asm("mov.b64 {%0,%1}, %2;" : "=f"(x), "=f"(y) : "l"(v));
}
#define FMA2(acc, a, b) asm("fma.rn.f32x2 %0, %1, %2, %0;" : "+l"(acc) : "l"(a), "l"(b))

__device__ __forceinline__ float sigm(float x) { return 1.0f / (1.0f + expf(-x)); }

// Stream one k-slice (16 k-columns) of a row-major [768][256] W into smem [k_local][j] (pad 769).
// Coalesced 64B global reads; transpose STS is bank-bijective with pad 769.
__device__ __forceinline__ void load_slice(const float* __restrict__ W, float* __restrict__ buf,
                                           int ks, int tid) {
    const float* Wk = W + ks * 16;
#pragma unroll
    for (int s = 0; s < 12; s++) {
        int fidx = tid + 256 * s;
        int j = fidx >> 2;
        int kq = fidx & 3;
        float4 v = *reinterpret_cast<const float4*>(Wk + j * 256 + kq * 4);
        float* d = buf + (kq * 4) * 769 + j;
        d[0] = v.x; d[769] = v.y; d[2 * 769] = v.z; d[3 * 769] = v.w;
    }
}

// ======================= encoder GRU: 32 CTAs x 2 batch rows =======================
__global__ void __launch_bounds__(256, 1)
enc_kernel(const float* __restrict__ X, const float* __restrict__ Wih,
           const float* __restrict__ Whh, const float* __restrict__ bih,
           const float* __restrict__ bhh) {
    extern __shared__ float sm[];
    float* sW   = sm;            // 2*16*769 = 24608
    float* sWih = sm + 24608;    // 768*33   = 25344
    float* sh   = sm + 49952;    // [k=256][4] = 1024 (b in 0..1)
    float* sbih = sm + 50976;    // 768
    float* sbhh = sm + 51744;    // 768
    float* sx   = sm + 52512;    // [i=32][4] = 128
    int tid = threadIdx.x;
    int b0 = blockIdx.x * 2;

#pragma unroll
    for (int s = 0; s < 24; s++) {   // W_ih_enc [768][32] -> smem [j][i] pad 33
        int fidx = tid + 256 * s;
        int j = fidx >> 3, iq = fidx & 7;
        float4 v = *reinterpret_cast<const float4*>(Wih + j * 32 + iq * 4);
        float* d = sWih + j * 33 + iq * 4;
        d[0] = v.x; d[1] = v.y; d[2] = v.z; d[3] = v.w;
    }
    for (int idx = tid; idx < 768; idx += 256) { sbih[idx] = bih[idx]; sbhh[idx] = bhh[idx]; }
    for (int idx = tid; idx < 1024; idx += 256) sh[idx] = 0.0f;
    if (tid < 64) { int b = tid >> 5, i = tid & 31; sx[i * 4 + b] = X[((b0 + b) * TSEQ + 0) * NP + i]; }
    __syncthreads();
    load_slice(Whh, sW, 0, tid);
    __syncthreads();
    int cur = 0;
    float bi0 = sbih[tid], bi1 = sbih[tid + 256], bi2 = sbih[tid + 512];
    float bh0 = sbhh[tid], bh1 = sbhh[tid + 256], bh2 = sbhh[tid + 512];

    for (int t = 0; t < 10; t++) {
        // input projection for this step (x is 32-wide)
        float g0a = bi0, g0b = bi0, g1a = bi1, g1b = bi1, g2a = bi2, g2b = bi2;
        const float* w0p = sWih + tid * 33;
        const float* w1p = sWih + (tid + 256) * 33;
        const float* w2p = sWih + (tid + 512) * 33;
#pragma unroll
        for (int i = 0; i < 32; i++) {
            float xa = sx[i * 4 + 0], xb = sx[i * 4 + 1];
            g0a += w0p[i] * xa; g0b += w0p[i] * xb;
            g1a += w1p[i] * xa; g1b += w1p[i] * xb;
            g2a += w2p[i] * xa; g2b += w2p[i] * xb;
        }
        ull acc0 = pk(bh0, bh0), acc1 = pk(bh1, bh1), acc2 = pk(bh2, bh2);
        for (int ks = 0; ks < 16; ks++) {
            load_slice(Whh, sW + (cur ^ 1) * 12304, (ks + 1) & 15, tid);
            const float* base = sW + cur * 12304;
#pragma unroll
            for (int kl = 0; kl < 16; kl++) {
                const float* wr = base + kl * 769;
                ull w0 = pk2(wr[tid]), w1 = pk2(wr[tid + 256]), w2 = pk2(wr[tid + 512]);
                ull h2 = *reinterpret_cast<const ull*>(sh + (ks * 16 + kl) * 4);
                FMA2(acc0, w0, h2); FMA2(acc1, w1, h2); FMA2(acc2, w2, h2);
            }
            __syncthreads();
            cur ^= 1;
        }
        float a0x, a0y, a1x, a1y, a2x, a2y;
        upk(acc0, a0x, a0y); upk(acc1, a1x, a1y); upk(acc2, a2x, a2y);
        float hn0, hn1;
        { float r = sigm(g0a + a0x), z = sigm(g1a + a1x);
          float n = tanhf(g2a + r * a2x);
          hn0 = (1.0f - z) * n + z * sh[tid * 4 + 0]; }
        { float r = sigm(g0b + a0y), z = sigm(g1b + a1y);
          float n = tanhf(g2b + r * a2y);
          hn1 = (1.0f - z) * n + z * sh[tid * 4 + 1]; }
        sh[tid * 4 + 0] = hn0; sh[tid * 4 + 1] = hn1;
        if (t < 9 && tid < 64) {
            int b = tid >> 5, i = tid & 31;
            sx[i * 4 + b] = X[((b0 + b) * TSEQ + (t + 1)) * NP + i];
        }
        __syncthreads();
    }
    g_henc[(b0 + 0) * NH + tid] = sh[tid * 4 + 0];
    g_henc[(b0 + 1) * NH + tid] = sh[tid * 4 + 1];
}

// ======================= latent: mu / log_var / z =======================
__global__ void lat_kernel(const float* __restrict__ eps, const float* __restrict__ mw,
                           const float* __restrict__ mb, const float* __restrict__ sw_,
                           const float* __restrict__ sb_, float* __restrict__ out) {
    __shared__ float hh[NH];
    int b = blockIdx.x, tid = threadIdx.x;
    hh[tid] = g_henc[b * NH + tid];
    __syncthreads();
    float am = mb[tid], as = sb_[tid];
    const float* mr = mw + tid * NH;
    const float* sr = sw_ + tid * NH;
#pragma unroll 8
    for (int k = 0; k < NH; k++) { float h = hh[k]; am += mr[k] * h; as += sr[k] * h; }
    out[126976 + b * NH + tid] = am;   // mu
    out[110592 + b * NH + tid] = as;   // log_var
    g_z[b * NH + tid] = am + expf(0.5f * as) * eps[b * NH + tid];
}

// ======================= decoder input projection (batched GEMM, K=32) =======================
__global__ void __launch_bounds__(256, 1)
gi_kernel(const float* __restrict__ X, const float* __restrict__ Wih_all,
          const float* __restrict__ bih_all) {
    extern __shared__ float sm[];
    float* sWih = sm;          // 768*33 = 25344
    float* sxT  = sm + 25344;  // [i=32][66] (b-major, pairs aligned)
    int tid = threadIdx.x;
    int t = blockIdx.x, p = blockIdx.y;
    const float* Wih = Wih_all + p * NG * NP;
#pragma unroll
    for (int s = 0; s < 24; s++) {
        int fidx = tid + 256 * s;
        int j = fidx >> 3, iq = fidx & 7;
        float4 v = *reinterpret_cast<const float4*>(Wih + j * 32 + iq * 4);
        float* d = sWih + j * 33 + iq * 4;
        d[0] = v.x; d[1] = v.y; d[2] = v.z; d[3] = v.w;
    }
    for (int idx = tid; idx < 2048; idx += 256) {
        int b = idx >> 5, i = idx & 31;
        // dec_in[b][t] = (t==0) ? 0 : X[b][9+t]
        sxT[i * 66 + b] = (t == 0) ? 0.0f : X[(b * TSEQ + 9 + t) * NP + i];
    }
    float bi0 = bih_all[p * NG + tid];
    float bi1 = bih_all[p * NG + 256 + tid];
    float bi2 = bih_all[p * NG + 512 + tid];
    __syncthreads();
    float* og = g_gi + ((size_t)(p * TDEC + t) * NB) * NG;
    for (int bg = 0; bg < 4; bg++) {
        ull a0[8], a1[8], a2[8];
#pragma unroll
        for (int g = 0; g < 8; g++) { a0[g] = pk2(bi0); a1[g] = pk2(bi1); a2[g] = pk2(bi2); }
#pragma unroll
        for (int i = 0; i < 32; i++) {
            ull w0 = pk2(sWih[tid * 33 + i]);
            ull w1 = pk2(sWih[(tid + 256) * 33 + i]);
            ull w2 = pk2(sWih[(tid + 512) * 33 + i]);
            const ull* xp = reinterpret_cast<const ull*>(sxT + i * 66 + bg * 16);
#pragma unroll
            for (int g = 0; g < 8; g++) {
                ull x2 = xp[g];
                FMA2(a0[g], w0, x2); FMA2(a1[g], w1, x2); FMA2(a2[g], w2, x2);
            }
        }
#pragma unroll
        for (int g = 0; g < 8; g++) {
            float x0, x1;
            int b = bg * 16 + 2 * g;
            upk(a0[g], x0, x1); og[(size_t)b * NG + tid] = x0;       og[(size_t)(b + 1) * NG + tid] = x1;
            upk(a1[g], x0, x1); og[(size_t)b * NG + 256 + tid] = x0; og[(size_t)(b + 1) * NG + 256 + tid] = x1;
            upk(a2[g], x0, x1); og[(size_t)b * NG + 512 + tid] = x0; og[(size_t)(b + 1) * NG + 512 + tid] = x1;
        }
    }
}

// ======================= decoder GRU: 128 CTAs = 32 series x 4 batch-chunks =======================
__global__ void __launch_bounds__(256, 1)
dec_kernel(const float* __restrict__ Whh_all, const float* __restrict__ bhh_all,
           const float* __restrict__ lw_all, const float* __restrict__ lb_all,
           float* __restrict__ out) {
    extern __shared__ float sm[];
    float* sW   = sm;           // 2*16*769 = 24608 (double-buffered k-slices of Whh)
    float* sh   = sm + 24608;   // [k=256][18] = 4608 (16 batch rows + pad)
    float* sbhh = sm + 29216;   // 768
    float* slw  = sm + 29984;   // 256
    int tid = threadIdx.x;
    int p = blockIdx.y, c = blockIdx.x, b0 = c * 16;
    const float* Whh = Whh_all + (size_t)p * NG * NH;
    for (int idx = tid; idx < 768; idx += 256) sbhh[idx] = bhh_all[p * NG + idx];
    slw[tid] = lw_all[p * NH + tid];
    float lb = lb_all[p];
    for (int idx = tid; idx < 4096; idx += 256) {
        int b = idx >> 8, k = idx & 255;
        sh[k * 18 + b] = g_z[(b0 + b) * NH + k];
    }
    __syncthreads();
    load_slice(Whh, sW, 0, tid);
    __syncthreads();
    int cur = 0;
    float bh0 = sbhh[tid], bh1 = sbhh[tid + 256], bh2 = sbhh[tid + 512];
    int w = tid >> 5, lane = tid & 31;

    for (int t = 0; t < TDEC; t++) {
        ull acc0[8], acc1[8], acc2[8];
#pragma unroll
        for (int g = 0; g < 8; g++) { acc0[g] = pk2(bh0); acc1[g] = pk2(bh1); acc2[g] = pk2(bh2); }

        for (int ks = 0; ks < 16; ks++) {
            load_slice(Whh, sW + (cur ^ 1) * 12304, (ks + 1) & 15, tid);
            const float* base = sW + cur * 12304;
#pragma unroll
            for (int kl = 0; kl < 16; kl++) {
                const float* wr = base + kl * 769;
                ull w0 = pk2(wr[tid]), w1 = pk2(wr[tid + 256]), w2 = pk2(wr[tid + 512]);
                const ull* hp = reinterpret_cast<const ull*>(sh + (ks * 16 + kl) * 18);
#pragma unroll
                for (int g = 0; g < 8; g++) {
                    ull h2 = hp[g];
                    FMA2(acc0[g], w0, h2); FMA2(acc1[g], w1, h2); FMA2(acc2[g], w2, h2);
                }
            }
            __syncthreads();
            cur ^= 1;
        }
        // gates + h update (thread owns hidden index i = tid for 16 batch rows)
        const float* gip = g_gi + ((size_t)(p * TDEC + t) * NB + b0) * NG + tid;
#pragma unroll
        for (int g = 0; g < 8; g++) {
            float a0x, a0y, a1x, a1y, a2x, a2y;
            upk(acc0[g], a0x, a0y); upk(acc1[g], a1x, a1y); upk(acc2[g], a2x, a2y);
            int b = 2 * g;
            {
                float gi0 = gip[(size_t)b * NG], gi1 = gip[(size_t)b * NG + 256], gi2 = gip[(size_t)b * NG + 512];
                float r = sigm(gi0 + a0x), z = sigm(gi1 + a1x);
                float n = tanhf(gi2 + r * a2x);
                sh[tid * 18 + b] = (1.0f - z) * n + z * sh[tid * 18 + b];
            }
            {
                float gi0 = gip[(size_t)(b + 1) * NG], gi1 = gip[(size_t)(b + 1) * NG + 256], gi2 = gip[(size_t)(b + 1) * NG + 512];
                float r = sigm(gi0 + a0y), z = sigm(gi1 + a1y);
                float n = tanhf(gi2 + r * a2y);
                sh[tid * 18 + b + 1] = (1.0f - z) * n + z * sh[tid * 18 + b + 1];
            }
        }
        __syncthreads();
        // linear head: warp w reduces batch rows 2w, 2w+1
#pragma unroll
        for (int rep = 0; rep < 2; rep++) {
            int b = w * 2 + rep;
            float s = 0.0f;
#pragma unroll
            for (int m = 0; m < 8; m++) { int k = lane + 32 * m; s += slw[k] * sh[k * 18 + b]; }
#pragma unroll
            for (int off = 16; off; off >>= 1) s += __shfl_xor_sync(0xffffffffu, s, off);
            if (lane == 0) out[((size_t)p * NB + b0 + b) * TDEC + t] = s + lb;
        }
    }
}

// ======================= launcher =======================
extern "C" void kernel_launch(void* const* d_in, const int* in_sizes, int n_in,
                              void* d_out, int out_size) {
    const float* X       = (const float*)d_in[0];
    const float* eps     = (const float*)d_in[1];
    const float* Wih_enc = (const float*)d_in[2];
    const float* Whh_enc = (const float*)d_in[3];
    const float* bih_enc = (const float*)d_in[4];
    const float* bhh_enc = (const float*)d_in[5];
    const float* mw      = (const float*)d_in[6];
    const float* mb      = (const float*)d_in[7];
    const float* sw      = (const float*)d_in[8];
    const float* sb      = (const float*)d_in[9];
    const float* Wih_dec = (const float*)d_in[10];
    const float* Whh_dec = (const float*)d_in[11];
    const float* bih_dec = (const float*)d_in[12];
    const float* bhh_dec = (const float*)d_in[13];
    const float* lw      = (const float*)d_in[14];
    const float* lbv     = (const float*)d_in[15];
    float* out = (float*)d_out;

    int smem_enc = 52640 * 4;   // 210,560 B
    int smem_gi  = (25344 + 32 * 66) * 4;  // 109,824 B
    int smem_dec = 30240 * 4;   // 120,960 B
    cudaFuncSetAttribute(enc_kernel, cudaFuncAttributeMaxDynamicSharedMemorySize, smem_enc);
    cudaFuncSetAttribute(gi_kernel,  cudaFuncAttributeMaxDynamicSharedMemorySize, smem_gi);
    cudaFuncSetAttribute(dec_kernel, cudaFuncAttributeMaxDynamicSharedMemorySize, smem_dec);

    gi_kernel<<<dim3(TDEC, NP), 256, smem_gi>>>(X, Wih_dec, bih_dec);
    enc_kernel<<<32, 256, smem_enc>>>(X, Wih_enc, Whh_enc, bih_enc, bhh_enc);
    lat_kernel<<<NB, 256>>>(eps, mw, mb, sw, sb, out);
    dec_kernel<<<dim3(4, NP), 256, smem_dec>>>(Whh_dec, bhh_dec, lw, lbv, out);
}

// round 5
// speedup vs baseline: 1.2304x; 1.2304x over previous
#include <cuda_runtime.h>
#include <math.h>

typedef unsigned long long ull;

#define NB 64
#define NH 256
#define NG 768
#define NP 32
#define TSEQ 64
#define TDEC 54

// -------- scratch (device globals; no allocation in kernel_launch) --------
__device__ float g_gi[84934656];   // [P=32][t=54][b=64][j=768] decoder input-proj (incl b_ih)
__device__ float g_z[NB * NH];     // latent z
__device__ float g_henc[NB * NH];  // encoder final hidden
__device__ float g_Wt[32 * 256 * 768];  // W_hh_dec transposed: [p][k=256][j=768]

// -------- f32x2 helpers --------
__device__ __forceinline__ ull pk(float x, float y) {
    ull r; asm("mov.b64 %0, {%1,%2};" : "=l"(r) : "f"(x), "f"(y)); return r;
}
__device__ __forceinline__ ull pk2(float x) { return pk(x, x); }
__device__ __forceinline__ void upk(ull v, float& x, float& y) {
    asm("mov.b64 {%0,%1}, %2;" : "=f"(x), "=f"(y) : "l"(v));
}
#define FMA2(acc, a, b) asm("fma.rn.f32x2 %0, %1, %2, %0;" : "+l"(acc) : "l"(a), "l"(b))

__device__ __forceinline__ float sigm(float x) { return 1.0f / (1.0f + expf(-x)); }

// (encoder path) Stream one k-slice (16 k-columns) of a row-major [768][256] W into
// smem [k_local][j] (pad 769). Coalesced reads; transpose STS is bank-bijective.
__device__ __forceinline__ void load_slice(const float* __restrict__ W, float* __restrict__ buf,
                                           int ks, int tid) {
    const float* Wk = W + ks * 16;
#pragma unroll
    for (int s = 0; s < 12; s++) {
        int fidx = tid + 256 * s;
        int j = fidx >> 2;
        int kq = fidx & 3;
        float4 v = *reinterpret_cast<const float4*>(Wk + j * 256 + kq * 4);
        float* d = buf + (kq * 4) * 769 + j;
        d[0] = v.x; d[769] = v.y; d[2 * 769] = v.z; d[3 * 769] = v.w;
    }
}

// (decoder path) Stream one 32-k slice of transposed W [k][j=768] into smem rows padded to 772.
// Pure float4 LDG + aligned STS.128, no transpose needed.
__device__ __forceinline__ void load_slice32(const float* __restrict__ Wt, float* __restrict__ buf,
                                             int ks, int tid) {
    const float4* src = reinterpret_cast<const float4*>(Wt + (size_t)ks * 32 * 768);
#pragma unroll
    for (int s = 0; s < 12; s++) {
        int fidx = tid + 512 * s;          // 0..6143 float4s
        int row = fidx / 192;              // 192 float4 per 768-float row
        int c4 = fidx - row * 192;
        float4 v = src[row * 192 + c4];
        *reinterpret_cast<float4*>(buf + row * 772 + c4 * 4) = v;
    }
}

// ======================= W_hh_dec transpose: [p][768][256] -> [p][256][768] =======================
__global__ void tr_kernel(const float* __restrict__ W) {
    __shared__ float tile[32][33];
    int p = blockIdx.z;
    int k0 = blockIdx.x * 32, j0 = blockIdx.y * 32;
    const float* Wp = W + (size_t)p * NG * NH;
    float* Wtp = g_Wt + (size_t)p * NH * NG;
    int x = threadIdx.x, y0 = threadIdx.y;   // block (32, 8)
#pragma unroll
    for (int dy = 0; dy < 32; dy += 8) {
        int j = j0 + y0 + dy;
        tile[y0 + dy][x] = Wp[(size_t)j * NH + k0 + x];
    }
    __syncthreads();
#pragma unroll
    for (int dy = 0; dy < 32; dy += 8) {
        int k = k0 + y0 + dy;
        Wtp[(size_t)k * NG + j0 + x] = tile[x][y0 + dy];
    }
}

// ======================= encoder GRU: 32 CTAs x 2 batch rows =======================
__global__ void __launch_bounds__(256, 1)
enc_kernel(const float* __restrict__ X, const float* __restrict__ Wih,
           const float* __restrict__ Whh, const float* __restrict__ bih,
           const float* __restrict__ bhh) {
    extern __shared__ float sm[];
    float* sW   = sm;            // 2*16*769 = 24608
    float* sWih = sm + 24608;    // 768*33   = 25344
    float* sh   = sm + 49952;    // [k=256][4]
    float* sbih = sm + 50976;    // 768
    float* sbhh = sm + 51744;    // 768
    float* sx   = sm + 52512;    // [i=32][4]
    int tid = threadIdx.x;
    int b0 = blockIdx.x * 2;

#pragma unroll
    for (int s = 0; s < 24; s++) {   // W_ih_enc [768][32] -> smem [j][i] pad 33
        int fidx = tid + 256 * s;
        int j = fidx >> 3, iq = fidx & 7;
        float4 v = *reinterpret_cast<const float4*>(Wih + j * 32 + iq * 4);
        float* d = sWih + j * 33 + iq * 4;
        d[0] = v.x; d[1] = v.y; d[2] = v.z; d[3] = v.w;
    }
    for (int idx = tid; idx < 768; idx += 256) { sbih[idx] = bih[idx]; sbhh[idx] = bhh[idx]; }
    for (int idx = tid; idx < 1024; idx += 256) sh[idx] = 0.0f;
    if (tid < 64) { int b = tid >> 5, i = tid & 31; sx[i * 4 + b] = X[((b0 + b) * TSEQ + 0) * NP + i]; }
    __syncthreads();
    load_slice(Whh, sW, 0, tid);
    __syncthreads();
    int cur = 0;
    float bi0 = sbih[tid], bi1 = sbih[tid + 256], bi2 = sbih[tid + 512];
    float bh0 = sbhh[tid], bh1 = sbhh[tid + 256], bh2 = sbhh[tid + 512];

    for (int t = 0; t < 10; t++) {
        float g0a = bi0, g0b = bi0, g1a = bi1, g1b = bi1, g2a = bi2, g2b = bi2;
        const float* w0p = sWih + tid * 33;
        const float* w1p = sWih + (tid + 256) * 33;
        const float* w2p = sWih + (tid + 512) * 33;
#pragma unroll
        for (int i = 0; i < 32; i++) {
            float xa = sx[i * 4 + 0], xb = sx[i * 4 + 1];
            g0a += w0p[i] * xa; g0b += w0p[i] * xb;
            g1a += w1p[i] * xa; g1b += w1p[i] * xb;
            g2a += w2p[i] * xa; g2b += w2p[i] * xb;
        }
        ull acc0 = pk(bh0, bh0), acc1 = pk(bh1, bh1), acc2 = pk(bh2, bh2);
        for (int ks = 0; ks < 16; ks++) {
            load_slice(Whh, sW + (cur ^ 1) * 12304, (ks + 1) & 15, tid);
            const float* base = sW + cur * 12304;
#pragma unroll
            for (int kl = 0; kl < 16; kl++) {
                const float* wr = base + kl * 769;
                ull w0 = pk2(wr[tid]), w1 = pk2(wr[tid + 256]), w2 = pk2(wr[tid + 512]);
                ull h2 = *reinterpret_cast<const ull*>(sh + (ks * 16 + kl) * 4);
                FMA2(acc0, w0, h2); FMA2(acc1, w1, h2); FMA2(acc2, w2, h2);
            }
            __syncthreads();
            cur ^= 1;
        }
        float a0x, a0y, a1x, a1y, a2x, a2y;
        upk(acc0, a0x, a0y); upk(acc1, a1x, a1y); upk(acc2, a2x, a2y);
        float hn0, hn1;
        { float r = sigm(g0a + a0x), z = sigm(g1a + a1x);
          float n = tanhf(g2a + r * a2x);
          hn0 = (1.0f - z) * n + z * sh[tid * 4 + 0]; }
        { float r = sigm(g0b + a0y), z = sigm(g1b + a1y);
          float n = tanhf(g2b + r * a2y);
          hn1 = (1.0f - z) * n + z * sh[tid * 4 + 1]; }
        sh[tid * 4 + 0] = hn0; sh[tid * 4 + 1] = hn1;
        if (t < 9 && tid < 64) {
            int b = tid >> 5, i = tid & 31;
            sx[i * 4 + b] = X[((b0 + b) * TSEQ + (t + 1)) * NP + i];
        }
        __syncthreads();
    }
    g_henc[(b0 + 0) * NH + tid] = sh[tid * 4 + 0];
    g_henc[(b0 + 1) * NH + tid] = sh[tid * 4 + 1];
}

// ======================= latent: mu / log_var / z =======================
__global__ void lat_kernel(const float* __restrict__ eps, const float* __restrict__ mw,
                           const float* __restrict__ mb, const float* __restrict__ sw_,
                           const float* __restrict__ sb_, float* __restrict__ out) {
    __shared__ float hh[NH];
    int b = blockIdx.x, tid = threadIdx.x;
    hh[tid] = g_henc[b * NH + tid];
    __syncthreads();
    float am = mb[tid], as = sb_[tid];
    const float* mr = mw + tid * NH;
    const float* sr = sw_ + tid * NH;
#pragma unroll 8
    for (int k = 0; k < NH; k++) { float h = hh[k]; am += mr[k] * h; as += sr[k] * h; }
    out[126976 + b * NH + tid] = am;   // mu
    out[110592 + b * NH + tid] = as;   // log_var
    g_z[b * NH + tid] = am + expf(0.5f * as) * eps[b * NH + tid];
}

// ======================= decoder input projection (batched GEMM, K=32) =======================
__global__ void __launch_bounds__(256, 1)
gi_kernel(const float* __restrict__ X, const float* __restrict__ Wih_all,
          const float* __restrict__ bih_all) {
    extern __shared__ float sm[];
    float* sWih = sm;          // 768*33 = 25344
    float* sxT  = sm + 25344;  // [i=32][66]
    int tid = threadIdx.x;
    int t = blockIdx.x, p = blockIdx.y;
    const float* Wih = Wih_all + p * NG * NP;
#pragma unroll
    for (int s = 0; s < 24; s++) {
        int fidx = tid + 256 * s;
        int j = fidx >> 3, iq = fidx & 7;
        float4 v = *reinterpret_cast<const float4*>(Wih + j * 32 + iq * 4);
        float* d = sWih + j * 33 + iq * 4;
        d[0] = v.x; d[1] = v.y; d[2] = v.z; d[3] = v.w;
    }
    for (int idx = tid; idx < 2048; idx += 256) {
        int b = idx >> 5, i = idx & 31;
        sxT[i * 66 + b] = (t == 0) ? 0.0f : X[(b * TSEQ + 9 + t) * NP + i];
    }
    float bi0 = bih_all[p * NG + tid];
    float bi1 = bih_all[p * NG + 256 + tid];
    float bi2 = bih_all[p * NG + 512 + tid];
    __syncthreads();
    float* og = g_gi + ((size_t)(p * TDEC + t) * NB) * NG;
    for (int bg = 0; bg < 4; bg++) {
        ull a0[8], a1[8], a2[8];
#pragma unroll
        for (int g = 0; g < 8; g++) { a0[g] = pk2(bi0); a1[g] = pk2(bi1); a2[g] = pk2(bi2); }
#pragma unroll
        for (int i = 0; i < 32; i++) {
            ull w0 = pk2(sWih[tid * 33 + i]);
            ull w1 = pk2(sWih[(tid + 256) * 33 + i]);
            ull w2 = pk2(sWih[(tid + 512) * 33 + i]);
            const ull* xp = reinterpret_cast<const ull*>(sxT + i * 66 + bg * 16);
#pragma unroll
            for (int g = 0; g < 8; g++) {
                ull x2 = xp[g];
                FMA2(a0[g], w0, x2); FMA2(a1[g], w1, x2); FMA2(a2[g], w2, x2);
            }
        }
#pragma unroll
        for (int g = 0; g < 8; g++) {
            float x0, x1;
            int b = bg * 16 + 2 * g;
            upk(a0[g], x0, x1); og[(size_t)b * NG + tid] = x0;       og[(size_t)(b + 1) * NG + tid] = x1;
            upk(a1[g], x0, x1); og[(size_t)b * NG + 256 + tid] = x0; og[(size_t)(b + 1) * NG + 256 + tid] = x1;
            upk(a2[g], x0, x1); og[(size_t)b * NG + 512 + tid] = x0; og[(size_t)(b + 1) * NG + 512 + tid] = x1;
        }
    }
}

// ======================= decoder GRU: 128 CTAs = 32 series x 4 batch-chunks, 512 thr =======================
__global__ void __launch_bounds__(512, 1)
dec_kernel(const float* __restrict__ bhh_all,
           const float* __restrict__ lw_all, const float* __restrict__ lb_all,
           float* __restrict__ out) {
    extern __shared__ float sm[];
    float* sW   = sm;           // 2 * 32 * 772 = 49408 (double-buffered 32-k slices of Wt)
    float* sh   = sm + 49408;   // [k=256][20] : cols 0..15 = batch rows, 16B-aligned pairs
    float* sbhh = sm + 54528;   // 768
    float* slw  = sm + 55296;   // 256
    int tid = threadIdx.x;
    int half = tid >> 8;        // 0: batch rows 0-7, 1: rows 8-15
    int tl = tid & 255;         // gate-row index base
    int p = blockIdx.y, c = blockIdx.x, b0 = c * 16;
    const float* Wt = g_Wt + (size_t)p * NH * NG;
    for (int idx = tid; idx < 768; idx += 512) sbhh[idx] = bhh_all[p * NG + idx];
    if (tid < 256) slw[tid] = lw_all[p * NH + tid];
    float lb = lb_all[p];
    for (int idx = tid; idx < 4096; idx += 512) {
        int b = idx >> 8, k = idx & 255;
        sh[k * 20 + b] = g_z[(b0 + b) * NH + k];
    }
    __syncthreads();
    load_slice32(Wt, sW, 0, tid);
    __syncthreads();
    int cur = 0;
    float bh0 = sbhh[tl], bh1 = sbhh[tl + 256], bh2 = sbhh[tl + 512];
    int w = tid >> 5, lane = tid & 31;

    for (int t = 0; t < TDEC; t++) {
        ull a0[4], a1[4], a2[4];
#pragma unroll
        for (int g = 0; g < 4; g++) { a0[g] = pk2(bh0); a1[g] = pk2(bh1); a2[g] = pk2(bh2); }

        for (int ks = 0; ks < 8; ks++) {
            load_slice32(Wt, sW + (cur ^ 1) * 24704, (ks + 1) & 7, tid);
            const float* base = sW + cur * 24704;
#pragma unroll
            for (int kl = 0; kl < 32; kl++) {
                const float* wr = base + kl * 772;
                ull w0 = pk2(wr[tl]), w1 = pk2(wr[tl + 256]), w2 = pk2(wr[tl + 512]);
                const ulonglong2* hp = reinterpret_cast<const ulonglong2*>(
                    sh + (ks * 32 + kl) * 20 + half * 8);
                ulonglong2 hA = hp[0];
                ulonglong2 hB = hp[1];
                FMA2(a0[0], w0, hA.x); FMA2(a0[1], w0, hA.y);
                FMA2(a0[2], w0, hB.x); FMA2(a0[3], w0, hB.y);
                FMA2(a1[0], w1, hA.x); FMA2(a1[1], w1, hA.y);
                FMA2(a1[2], w1, hB.x); FMA2(a1[3], w1, hB.y);
                FMA2(a2[0], w2, hA.x); FMA2(a2[1], w2, hA.y);
                FMA2(a2[2], w2, hB.x); FMA2(a2[3], w2, hB.y);
            }
            __syncthreads();
            cur ^= 1;
        }
        // gates + h update: thread owns gate row tl for batch rows half*8 .. half*8+7
        const float* gip = g_gi + (((size_t)(p * TDEC + t) * NB) + b0 + half * 8) * NG + tl;
#pragma unroll
        for (int g = 0; g < 4; g++) {
            float a0x, a0y, a1x, a1y, a2x, a2y;
            upk(a0[g], a0x, a0y); upk(a1[g], a1x, a1y); upk(a2[g], a2x, a2y);
            int b = 2 * g;                 // local (within this half) batch row
            int bs = half * 8 + b;         // row within chunk
            {
                float gi0 = gip[(size_t)b * NG], gi1 = gip[(size_t)b * NG + 256], gi2 = gip[(size_t)b * NG + 512];
                float r = sigm(gi0 + a0x), z = sigm(gi1 + a1x);
                float n = tanhf(gi2 + r * a2x);
                sh[tl * 20 + bs] = (1.0f - z) * n + z * sh[tl * 20 + bs];
            }
            {
                float gi0 = gip[(size_t)(b + 1) * NG], gi1 = gip[(size_t)(b + 1) * NG + 256], gi2 = gip[(size_t)(b + 1) * NG + 512];
                float r = sigm(gi0 + a0y), z = sigm(gi1 + a1y);
                float n = tanhf(gi2 + r * a2y);
                sh[tl * 20 + bs + 1] = (1.0f - z) * n + z * sh[tl * 20 + bs + 1];
            }
        }
        __syncthreads();
        // linear head: warp w reduces batch row w (16 warps, 16 rows)
        {
            float s = 0.0f;
#pragma unroll
            for (int m = 0; m < 8; m++) { int k = lane + 32 * m; s += slw[k] * sh[k * 20 + w]; }
#pragma unroll
            for (int off = 16; off; off >>= 1) s += __shfl_xor_sync(0xffffffffu, s, off);
            if (lane == 0) out[((size_t)p * NB + b0 + w) * TDEC + t] = s + lb;
        }
    }
}

// ======================= launcher =======================
extern "C" void kernel_launch(void* const* d_in, const int* in_sizes, int n_in,
                              void* d_out, int out_size) {
    const float* X       = (const float*)d_in[0];
    const float* eps     = (const float*)d_in[1];
    const float* Wih_enc = (const float*)d_in[2];
    const float* Whh_enc = (const float*)d_in[3];
    const float* bih_enc = (const float*)d_in[4];
    const float* bhh_enc = (const float*)d_in[5];
    const float* mw      = (const float*)d_in[6];
    const float* mb      = (const float*)d_in[7];
    const float* sw      = (const float*)d_in[8];
    const float* sb      = (const float*)d_in[9];
    const float* Wih_dec = (const float*)d_in[10];
    const float* Whh_dec = (const float*)d_in[11];
    const float* bih_dec = (const float*)d_in[12];
    const float* bhh_dec = (const float*)d_in[13];
    const float* lw      = (const float*)d_in[14];
    const float* lbv     = (const float*)d_in[15];
    float* out = (float*)d_out;

    int smem_enc = 52640 * 4;              // 210,560 B
    int smem_gi  = (25344 + 32 * 66) * 4;  // 109,824 B
    int smem_dec = 55552 * 4;              // 222,208 B
    cudaFuncSetAttribute(enc_kernel, cudaFuncAttributeMaxDynamicSharedMemorySize, smem_enc);
    cudaFuncSetAttribute(gi_kernel,  cudaFuncAttributeMaxDynamicSharedMemorySize, smem_gi);
    cudaFuncSetAttribute(dec_kernel, cudaFuncAttributeMaxDynamicSharedMemorySize, smem_dec);

    tr_kernel<<<dim3(8, 24, 32), dim3(32, 8)>>>(Whh_dec);
    gi_kernel<<<dim3(TDEC, NP), 256, smem_gi>>>(X, Wih_dec, bih_dec);
    enc_kernel<<<32, 256, smem_enc>>>(X, Wih_enc, Whh_enc, bih_enc, bhh_enc);
    lat_kernel<<<NB, 256>>>(eps, mw, mb, sw, sb, out);
    dec_kernel<<<dim3(4, NP), 512, smem_dec>>>(bhh_dec, lw, lbv, out);
}

// round 6
// speedup vs baseline: 1.3568x; 1.1028x over previous
#include <cuda_runtime.h>
#include <math.h>

typedef unsigned long long ull;

#define NB 64
#define NH 256
#define NG 768
#define NP 32
#define TSEQ 64
#define TDEC 54

// -------- scratch (device globals; no allocation in kernel_launch) --------
__device__ float g_gi[84934656];   // [P=32][t=54][b=64][j=768] decoder input-proj (incl b_ih)
__device__ float g_z[NB * NH];     // latent z
__device__ float g_henc[NB * NH];  // encoder final hidden
__device__ float g_Wt[32 * 256 * 768];  // W_hh_dec transposed: [p][k=256][j=768]
__device__ float g_mwT[NH * NH];   // fc_mu_w transposed  [k][j]
__device__ float g_swT[NH * NH];   // fc_std_w transposed [k][j]

// -------- f32x2 helpers --------
__device__ __forceinline__ ull pk(float x, float y) {
    ull r; asm("mov.b64 %0, {%1,%2};" : "=l"(r) : "f"(x), "f"(y)); return r;
}
__device__ __forceinline__ ull pk2(float x) { return pk(x, x); }
__device__ __forceinline__ void upk(ull v, float& x, float& y) {
    asm("mov.b64 {%0,%1}, %2;" : "=f"(x), "=f"(y) : "l"(v));
}
#define FMA2(acc, a, b) asm("fma.rn.f32x2 %0, %1, %2, %0;" : "+l"(acc) : "l"(a), "l"(b))

__device__ __forceinline__ float sigm(float x) { return 1.0f / (1.0f + expf(-x)); }

// (encoder path) Stream one k-slice (16 k-columns) of a row-major [768][256] W into
// smem [k_local][j] (pad 769). Coalesced reads; transpose STS is bank-bijective.
__device__ __forceinline__ void load_slice(const float* __restrict__ W, float* __restrict__ buf,
                                           int ks, int tid) {
    const float* Wk = W + ks * 16;
#pragma unroll
    for (int s = 0; s < 12; s++) {
        int fidx = tid + 256 * s;
        int j = fidx >> 2;
        int kq = fidx & 3;
        float4 v = *reinterpret_cast<const float4*>(Wk + j * 256 + kq * 4);
        float* d = buf + (kq * 4) * 769 + j;
        d[0] = v.x; d[769] = v.y; d[2 * 769] = v.z; d[3 * 769] = v.w;
    }
}

// (decoder path) Stream one 32-k slice of transposed W [k][j=768] into smem rows padded to 772.
// Pure float4 LDG + aligned STS.128, no transpose needed.
__device__ __forceinline__ void load_slice32(const float* __restrict__ Wt, float* __restrict__ buf,
                                             int ks, int tid) {
    const float4* src = reinterpret_cast<const float4*>(Wt + (size_t)ks * 32 * 768);
#pragma unroll
    for (int s = 0; s < 12; s++) {
        int fidx = tid + 512 * s;          // 0..6143 float4s
        int row = fidx / 192;              // 192 float4 per 768-float row
        int c4 = fidx - row * 192;
        float4 v = src[row * 192 + c4];
        *reinterpret_cast<float4*>(buf + row * 772 + c4 * 4) = v;
    }
}

// ======================= W_hh_dec transpose: [p][768][256] -> [p][256][768] =======================
__global__ void tr_kernel(const float* __restrict__ W) {
    __shared__ float tile[32][33];
    int p = blockIdx.z;
    int k0 = blockIdx.x * 32, j0 = blockIdx.y * 32;
    const float* Wp = W + (size_t)p * NG * NH;
    float* Wtp = g_Wt + (size_t)p * NH * NG;
    int x = threadIdx.x, y0 = threadIdx.y;   // block (32, 8)
#pragma unroll
    for (int dy = 0; dy < 32; dy += 8) {
        int j = j0 + y0 + dy;
        tile[y0 + dy][x] = Wp[(size_t)j * NH + k0 + x];
    }
    __syncthreads();
#pragma unroll
    for (int dy = 0; dy < 32; dy += 8) {
        int k = k0 + y0 + dy;
        Wtp[(size_t)k * NG + j0 + x] = tile[x][y0 + dy];
    }
}

// ======================= fc weight transpose: [256][256] -> [256][256]^T (x2 matrices) ==========
__global__ void trf_kernel(const float* __restrict__ mw, const float* __restrict__ sw_) {
    __shared__ float tile[32][33];
    int sel = blockIdx.z;
    const float* Wp = sel ? sw_ : mw;
    float* Wtp = sel ? g_swT : g_mwT;
    int k0 = blockIdx.x * 32, j0 = blockIdx.y * 32;
    int x = threadIdx.x, y0 = threadIdx.y;   // block (32, 8)
#pragma unroll
    for (int dy = 0; dy < 32; dy += 8) {
        int j = j0 + y0 + dy;
        tile[y0 + dy][x] = Wp[j * NH + k0 + x];
    }
    __syncthreads();
#pragma unroll
    for (int dy = 0; dy < 32; dy += 8) {
        int k = k0 + y0 + dy;
        Wtp[k * NH + j0 + x] = tile[x][y0 + dy];
    }
}

// ======================= encoder GRU: 32 CTAs x 2 batch rows =======================
__global__ void __launch_bounds__(256, 1)
enc_kernel(const float* __restrict__ X, const float* __restrict__ Wih,
           const float* __restrict__ Whh, const float* __restrict__ bih,
           const float* __restrict__ bhh) {
    extern __shared__ float sm[];
    float* sW   = sm;            // 2*16*769 = 24608
    float* sWih = sm + 24608;    // 768*33   = 25344
    float* sh   = sm + 49952;    // [k=256][4]
    float* sbih = sm + 50976;    // 768
    float* sbhh = sm + 51744;    // 768
    float* sx   = sm + 52512;    // [i=32][4]
    int tid = threadIdx.x;
    int b0 = blockIdx.x * 2;

#pragma unroll
    for (int s = 0; s < 24; s++) {   // W_ih_enc [768][32] -> smem [j][i] pad 33
        int fidx = tid + 256 * s;
        int j = fidx >> 3, iq = fidx & 7;
        float4 v = *reinterpret_cast<const float4*>(Wih + j * 32 + iq * 4);
        float* d = sWih + j * 33 + iq * 4;
        d[0] = v.x; d[1] = v.y; d[2] = v.z; d[3] = v.w;
    }
    for (int idx = tid; idx < 768; idx += 256) { sbih[idx] = bih[idx]; sbhh[idx] = bhh[idx]; }
    for (int idx = tid; idx < 1024; idx += 256) sh[idx] = 0.0f;
    if (tid < 64) { int b = tid >> 5, i = tid & 31; sx[i * 4 + b] = X[((b0 + b) * TSEQ + 0) * NP + i]; }
    __syncthreads();
    load_slice(Whh, sW, 0, tid);
    __syncthreads();
    int cur = 0;
    float bi0 = sbih[tid], bi1 = sbih[tid + 256], bi2 = sbih[tid + 512];
    float bh0 = sbhh[tid], bh1 = sbhh[tid + 256], bh2 = sbhh[tid + 512];

    for (int t = 0; t < 10; t++) {
        float g0a = bi0, g0b = bi0, g1a = bi1, g1b = bi1, g2a = bi2, g2b = bi2;
        const float* w0p = sWih + tid * 33;
        const float* w1p = sWih + (tid + 256) * 33;
        const float* w2p = sWih + (tid + 512) * 33;
#pragma unroll
        for (int i = 0; i < 32; i++) {
            float xa = sx[i * 4 + 0], xb = sx[i * 4 + 1];
            g0a += w0p[i] * xa; g0b += w0p[i] * xb;
            g1a += w1p[i] * xa; g1b += w1p[i] * xb;
            g2a += w2p[i] * xa; g2b += w2p[i] * xb;
        }
        ull acc0 = pk(bh0, bh0), acc1 = pk(bh1, bh1), acc2 = pk(bh2, bh2);
        for (int ks = 0; ks < 16; ks++) {
            load_slice(Whh, sW + (cur ^ 1) * 12304, (ks + 1) & 15, tid);
            const float* base = sW + cur * 12304;
#pragma unroll
            for (int kl = 0; kl < 16; kl++) {
                const float* wr = base + kl * 769;
                ull w0 = pk2(wr[tid]), w1 = pk2(wr[tid + 256]), w2 = pk2(wr[tid + 512]);
                ull h2 = *reinterpret_cast<const ull*>(sh + (ks * 16 + kl) * 4);
                FMA2(acc0, w0, h2); FMA2(acc1, w1, h2); FMA2(acc2, w2, h2);
            }
            __syncthreads();
            cur ^= 1;
        }
        float a0x, a0y, a1x, a1y, a2x, a2y;
        upk(acc0, a0x, a0y); upk(acc1, a1x, a1y); upk(acc2, a2x, a2y);
        float hn0, hn1;
        { float r = sigm(g0a + a0x), z = sigm(g1a + a1x);
          float n = tanhf(g2a + r * a2x);
          hn0 = (1.0f - z) * n + z * sh[tid * 4 + 0]; }
        { float r = sigm(g0b + a0y), z = sigm(g1b + a1y);
          float n = tanhf(g2b + r * a2y);
          hn1 = (1.0f - z) * n + z * sh[tid * 4 + 1]; }
        sh[tid * 4 + 0] = hn0; sh[tid * 4 + 1] = hn1;
        if (t < 9 && tid < 64) {
            int b = tid >> 5, i = tid & 31;
            sx[i * 4 + b] = X[((b0 + b) * TSEQ + (t + 1)) * NP + i];
        }
        __syncthreads();
    }
    g_henc[(b0 + 0) * NH + tid] = sh[tid * 4 + 0];
    g_henc[(b0 + 1) * NH + tid] = sh[tid * 4 + 1];
}

// ======================= latent: mu / log_var / z (coalesced via transposed fc weights) ==========
__global__ void __launch_bounds__(256)
lat_kernel(const float* __restrict__ eps, const float* __restrict__ mb,
           const float* __restrict__ sb_, float* __restrict__ out) {
    __shared__ float hh[NH];
    int b = blockIdx.x, tid = threadIdx.x;
    hh[tid] = g_henc[b * NH + tid];
    __syncthreads();
    float am = mb[tid], as = sb_[tid];
    const float* mT = g_mwT + tid;
    const float* sT = g_swT + tid;
#pragma unroll 8
    for (int k = 0; k < NH; k++) {
        float h = hh[k];
        am += mT[k * NH] * h;   // coalesced: consecutive tid -> consecutive addresses
        as += sT[k * NH] * h;
    }
    out[126976 + b * NH + tid] = am;   // mu
    out[110592 + b * NH + tid] = as;   // log_var
    g_z[b * NH + tid] = am + expf(0.5f * as) * eps[b * NH + tid];
}

// ======================= decoder input projection (batched GEMM, K=32) =======================
__global__ void __launch_bounds__(256, 1)
gi_kernel(const float* __restrict__ X, const float* __restrict__ Wih_all,
          const float* __restrict__ bih_all) {
    extern __shared__ float sm[];
    float* sWih = sm;          // 768*33 = 25344
    float* sxT  = sm + 25344;  // [i=32][66]
    int tid = threadIdx.x;
    int t = blockIdx.x, p = blockIdx.y;
    const float* Wih = Wih_all + p * NG * NP;
#pragma unroll
    for (int s = 0; s < 24; s++) {
        int fidx = tid + 256 * s;
        int j = fidx >> 3, iq = fidx & 7;
        float4 v = *reinterpret_cast<const float4*>(Wih + j * 32 + iq * 4);
        float* d = sWih + j * 33 + iq * 4;
        d[0] = v.x; d[1] = v.y; d[2] = v.z; d[3] = v.w;
    }
    for (int idx = tid; idx < 2048; idx += 256) {
        int b = idx >> 5, i = idx & 31;
        sxT[i * 66 + b] = (t == 0) ? 0.0f : X[(b * TSEQ + 9 + t) * NP + i];
    }
    float bi0 = bih_all[p * NG + tid];
    float bi1 = bih_all[p * NG + 256 + tid];
    float bi2 = bih_all[p * NG + 512 + tid];
    __syncthreads();
    float* og = g_gi + ((size_t)(p * TDEC + t) * NB) * NG;
    for (int bg = 0; bg < 4; bg++) {
        ull a0[8], a1[8], a2[8];
#pragma unroll
        for (int g = 0; g < 8; g++) { a0[g] = pk2(bi0); a1[g] = pk2(bi1); a2[g] = pk2(bi2); }
#pragma unroll
        for (int i = 0; i < 32; i++) {
            ull w0 = pk2(sWih[tid * 33 + i]);
            ull w1 = pk2(sWih[(tid + 256) * 33 + i]);
            ull w2 = pk2(sWih[(tid + 512) * 33 + i]);
            const ull* xp = reinterpret_cast<const ull*>(sxT + i * 66 + bg * 16);
#pragma unroll
            for (int g = 0; g < 8; g++) {
                ull x2 = xp[g];
                FMA2(a0[g], w0, x2); FMA2(a1[g], w1, x2); FMA2(a2[g], w2, x2);
            }
        }
#pragma unroll
        for (int g = 0; g < 8; g++) {
            float x0, x1;
            int b = bg * 16 + 2 * g;
            upk(a0[g], x0, x1); og[(size_t)b * NG + tid] = x0;       og[(size_t)(b + 1) * NG + tid] = x1;
            upk(a1[g], x0, x1); og[(size_t)b * NG + 256 + tid] = x0; og[(size_t)(b + 1) * NG + 256 + tid] = x1;
            upk(a2[g], x0, x1); og[(size_t)b * NG + 512 + tid] = x0; og[(size_t)(b + 1) * NG + 512 + tid] = x1;
        }
    }
}

// ======================= decoder GRU: 128 CTAs = 32 series x 4 batch-chunks, 512 thr =======================
__global__ void __launch_bounds__(512, 1)
dec_kernel(const float* __restrict__ bhh_all,
           const float* __restrict__ lw_all, const float* __restrict__ lb_all,
           float* __restrict__ out) {
    extern __shared__ float sm[];
    float* sW   = sm;           // 2 * 32 * 772 = 49408 (double-buffered 32-k slices of Wt)
    float* sh   = sm + 49408;   // [k=256][20] : cols 0..15 = batch rows, 16B-aligned pairs
    float* sbhh = sm + 54528;   // 768
    float* slw  = sm + 55296;   // 256
    int tid = threadIdx.x;
    int half = tid >> 8;        // 0: batch rows 0-7, 1: rows 8-15
    int tl = tid & 255;         // gate-row index base
    int p = blockIdx.y, c = blockIdx.x, b0 = c * 16;
    const float* Wt = g_Wt + (size_t)p * NH * NG;
    for (int idx = tid; idx < 768; idx += 512) sbhh[idx] = bhh_all[p * NG + idx];
    if (tid < 256) slw[tid] = lw_all[p * NH + tid];
    float lb = lb_all[p];
    for (int idx = tid; idx < 4096; idx += 512) {
        int b = idx >> 8, k = idx & 255;
        sh[k * 20 + b] = g_z[(b0 + b) * NH + k];
    }
    __syncthreads();
    load_slice32(Wt, sW, 0, tid);
    __syncthreads();
    int cur = 0;
    float bh0 = sbhh[tl], bh1 = sbhh[tl + 256], bh2 = sbhh[tl + 512];
    int w = tid >> 5, lane = tid & 31;

    for (int t = 0; t < TDEC; t++) {
        // ---- prefetch this step's gi (24 scalar, coalesced across tl) BEFORE the FMA loop ----
        const float* gip = g_gi + (((size_t)(p * TDEC + t) * NB) + b0 + half * 8) * NG + tl;
        float pg[24];
#pragma unroll
        for (int b = 0; b < 8; b++) {
            pg[b * 3 + 0] = gip[(size_t)b * NG];
            pg[b * 3 + 1] = gip[(size_t)b * NG + 256];
            pg[b * 3 + 2] = gip[(size_t)b * NG + 512];
        }

        ull a0[4], a1[4], a2[4];
#pragma unroll
        for (int g = 0; g < 4; g++) { a0[g] = pk2(bh0); a1[g] = pk2(bh1); a2[g] = pk2(bh2); }

        for (int ks = 0; ks < 8; ks++) {
            load_slice32(Wt, sW + (cur ^ 1) * 24704, (ks + 1) & 7, tid);
            const float* base = sW + cur * 24704;
#pragma unroll
            for (int kl = 0; kl < 32; kl++) {
                const float* wr = base + kl * 772;
                ull w0 = pk2(wr[tl]), w1 = pk2(wr[tl + 256]), w2 = pk2(wr[tl + 512]);
                const ulonglong2* hp = reinterpret_cast<const ulonglong2*>(
                    sh + (ks * 32 + kl) * 20 + half * 8);
                ulonglong2 hA = hp[0];
                ulonglong2 hB = hp[1];
                FMA2(a0[0], w0, hA.x); FMA2(a0[1], w0, hA.y);
                FMA2(a0[2], w0, hB.x); FMA2(a0[3], w0, hB.y);
                FMA2(a1[0], w1, hA.x); FMA2(a1[1], w1, hA.y);
                FMA2(a1[2], w1, hB.x); FMA2(a1[3], w1, hB.y);
                FMA2(a2[0], w2, hA.x); FMA2(a2[1], w2, hA.y);
                FMA2(a2[2], w2, hB.x); FMA2(a2[3], w2, hB.y);
            }
            __syncthreads();
            cur ^= 1;
        }
        // gates + h update: thread owns gate row tl for batch rows half*8 .. half*8+7
#pragma unroll
        for (int g = 0; g < 4; g++) {
            float a0x, a0y, a1x, a1y, a2x, a2y;
            upk(a0[g], a0x, a0y); upk(a1[g], a1x, a1y); upk(a2[g], a2x, a2y);
            int b = 2 * g;                 // local (within this half) batch row
            int bs = half * 8 + b;         // row within chunk
            {
                float r = sigm(pg[b * 3 + 0] + a0x), z = sigm(pg[b * 3 + 1] + a1x);
                float n = tanhf(pg[b * 3 + 2] + r * a2x);
                sh[tl * 20 + bs] = (1.0f - z) * n + z * sh[tl * 20 + bs];
            }
            {
                float r = sigm(pg[(b + 1) * 3 + 0] + a0y), z = sigm(pg[(b + 1) * 3 + 1] + a1y);
                float n = tanhf(pg[(b + 1) * 3 + 2] + r * a2y);
                sh[tl * 20 + bs + 1] = (1.0f - z) * n + z * sh[tl * 20 + bs + 1];
            }
        }
        __syncthreads();
        // linear head: warp w reduces batch row w (16 warps, 16 rows)
        {
            float s = 0.0f;
#pragma unroll
            for (int m = 0; m < 8; m++) { int k = lane + 32 * m; s += slw[k] * sh[k * 20 + w]; }
#pragma unroll
            for (int off = 16; off; off >>= 1) s += __shfl_xor_sync(0xffffffffu, s, off);
            if (lane == 0) out[((size_t)p * NB + b0 + w) * TDEC + t] = s + lb;
        }
    }
}

// ======================= launcher =======================
extern "C" void kernel_launch(void* const* d_in, const int* in_sizes, int n_in,
                              void* d_out, int out_size) {
    const float* X       = (const float*)d_in[0];
    const float* eps     = (const float*)d_in[1];
    const float* Wih_enc = (const float*)d_in[2];
    const float* Whh_enc = (const float*)d_in[3];
    const float* bih_enc = (const float*)d_in[4];
    const float* bhh_enc = (const float*)d_in[5];
    const float* mw      = (const float*)d_in[6];
    const float* mb      = (const float*)d_in[7];
    const float* sw      = (const float*)d_in[8];
    const float* sb      = (const float*)d_in[9];
    const float* Wih_dec = (const float*)d_in[10];
    const float* Whh_dec = (const float*)d_in[11];
    const float* bih_dec = (const float*)d_in[12];
    const float* bhh_dec = (const float*)d_in[13];
    const float* lw      = (const float*)d_in[14];
    const float* lbv     = (const float*)d_in[15];
    float* out = (float*)d_out;

    int smem_enc = 52640 * 4;              // 210,560 B
    int smem_gi  = (25344 + 32 * 66) * 4;  // 109,824 B
    int smem_dec = 55552 * 4;              // 222,208 B
    cudaFuncSetAttribute(enc_kernel, cudaFuncAttributeMaxDynamicSharedMemorySize, smem_enc);
    cudaFuncSetAttribute(gi_kernel,  cudaFuncAttributeMaxDynamicSharedMemorySize, smem_gi);
    cudaFuncSetAttribute(dec_kernel, cudaFuncAttributeMaxDynamicSharedMemorySize, smem_dec);

    tr_kernel<<<dim3(8, 24, 32), dim3(32, 8)>>>(Whh_dec);
    trf_kernel<<<dim3(8, 8, 2), dim3(32, 8)>>>(mw, sw);
    gi_kernel<<<dim3(TDEC, NP), 256, smem_gi>>>(X, Wih_dec, bih_dec);
    enc_kernel<<<32, 256, smem_enc>>>(X, Wih_enc, Whh_enc, bih_enc, bhh_enc);
    lat_kernel<<<NB, 256>>>(eps, mb, sb, out);
    dec_kernel<<<dim3(4, NP), 512, smem_dec>>>(bhh_dec, lw, lbv, out);
}

// round 7
// speedup vs baseline: 1.3793x; 1.0165x over previous
#include <cuda_runtime.h>
#include <math.h>

typedef unsigned long long ull;

#define NB 64
#define NH 256
#define NG 768
#define NP 32
#define TSEQ 64
#define TDEC 54

// -------- scratch (device globals; no allocation in kernel_launch) --------
__device__ float g_gi[84934656];   // [P=32][t=54][b=64][j=768] decoder input-proj (incl b_ih)
__device__ float g_z[NB * NH];     // latent z
__device__ float g_henc[NB * NH];  // encoder final hidden
__device__ float g_Wt[32 * 256 * 768];  // W_hh_dec transposed: [p][k=256][j=768]
__device__ float g_WtEnc[256 * 768];    // W_hh_enc transposed: [k=256][j=768]
__device__ float g_mwT[NH * NH];   // fc_mu_w transposed  [k][j]
__device__ float g_swT[NH * NH];   // fc_std_w transposed [k][j]

// -------- f32x2 helpers --------
__device__ __forceinline__ ull pk(float x, float y) {
    ull r; asm("mov.b64 %0, {%1,%2};" : "=l"(r) : "f"(x), "f"(y)); return r;
}
__device__ __forceinline__ ull pk2(float x) { return pk(x, x); }
__device__ __forceinline__ void upk(ull v, float& x, float& y) {
    asm("mov.b64 {%0,%1}, %2;" : "=f"(x), "=f"(y) : "l"(v));
}
#define FMA2(acc, a, b) asm("fma.rn.f32x2 %0, %1, %2, %0;" : "+l"(acc) : "l"(a), "l"(b))

__device__ __forceinline__ float sigm(float x) { return 1.0f / (1.0f + expf(-x)); }

// Stream one 32-k slice of transposed W [k][j=768] into smem rows padded to 772 (512 threads).
__device__ __forceinline__ void load_slice32(const float* __restrict__ Wt, float* __restrict__ buf,
                                             int ks, int tid) {
    const float4* src = reinterpret_cast<const float4*>(Wt + (size_t)ks * 32 * 768);
#pragma unroll
    for (int s = 0; s < 12; s++) {
        int fidx = tid + 512 * s;          // 0..6143 float4s
        int row = fidx / 192;              // 192 float4 per 768-float row
        int c4 = fidx - row * 192;
        float4 v = src[row * 192 + c4];
        *reinterpret_cast<float4*>(buf + row * 772 + c4 * 4) = v;
    }
}

// Stream one 16-k slice of transposed W [k][j=768] into smem rows padded to 772 (512 threads).
__device__ __forceinline__ void load_slice16(const float* __restrict__ Wt, float* __restrict__ buf,
                                             int ks, int tid) {
    const float4* src = reinterpret_cast<const float4*>(Wt + (size_t)ks * 16 * 768);
#pragma unroll
    for (int s = 0; s < 6; s++) {
        int fidx = tid + 512 * s;          // 0..3071 float4s
        int row = fidx / 192;
        int c4 = fidx - row * 192;
        float4 v = src[row * 192 + c4];
        *reinterpret_cast<float4*>(buf + row * 772 + c4 * 4) = v;
    }
}

// ======================= W_hh_dec transpose: [p][768][256] -> [p][256][768] =======================
__global__ void tr_kernel(const float* __restrict__ W) {
    __shared__ float tile[32][33];
    int p = blockIdx.z;
    int k0 = blockIdx.x * 32, j0 = blockIdx.y * 32;
    const float* Wp = W + (size_t)p * NG * NH;
    float* Wtp = g_Wt + (size_t)p * NH * NG;
    int x = threadIdx.x, y0 = threadIdx.y;   // block (32, 8)
#pragma unroll
    for (int dy = 0; dy < 32; dy += 8) {
        int j = j0 + y0 + dy;
        tile[y0 + dy][x] = Wp[(size_t)j * NH + k0 + x];
    }
    __syncthreads();
#pragma unroll
    for (int dy = 0; dy < 32; dy += 8) {
        int k = k0 + y0 + dy;
        Wtp[(size_t)k * NG + j0 + x] = tile[x][y0 + dy];
    }
}

// ======================= W_hh_enc transpose: [768][256] -> [256][768] =======================
__global__ void tr_enc_kernel(const float* __restrict__ W) {
    __shared__ float tile[32][33];
    int k0 = blockIdx.x * 32, j0 = blockIdx.y * 32;
    int x = threadIdx.x, y0 = threadIdx.y;   // block (32, 8)
#pragma unroll
    for (int dy = 0; dy < 32; dy += 8) {
        int j = j0 + y0 + dy;
        tile[y0 + dy][x] = W[j * NH + k0 + x];
    }
    __syncthreads();
#pragma unroll
    for (int dy = 0; dy < 32; dy += 8) {
        int k = k0 + y0 + dy;
        g_WtEnc[k * NG + j0 + x] = tile[x][y0 + dy];
    }
}

// ======================= fc weight transpose: [256][256] -> [256][256]^T (x2 matrices) ==========
__global__ void trf_kernel(const float* __restrict__ mw, const float* __restrict__ sw_) {
    __shared__ float tile[32][33];
    int sel = blockIdx.z;
    const float* Wp = sel ? sw_ : mw;
    float* Wtp = sel ? g_swT : g_mwT;
    int k0 = blockIdx.x * 32, j0 = blockIdx.y * 32;
    int x = threadIdx.x, y0 = threadIdx.y;   // block (32, 8)
#pragma unroll
    for (int dy = 0; dy < 32; dy += 8) {
        int j = j0 + y0 + dy;
        tile[y0 + dy][x] = Wp[j * NH + k0 + x];
    }
    __syncthreads();
#pragma unroll
    for (int dy = 0; dy < 32; dy += 8) {
        int k = k0 + y0 + dy;
        Wtp[k * NH + j0 + x] = tile[x][y0 + dy];
    }
}

// ======================= encoder GRU: 16 CTAs x 4 batch rows, 512 threads =======================
// smem (floats): sW 0..24704 (2x16x772), sWih 24704..50048 ([768][33]),
//                sh 50048..51072 ([k=256][4]), sbih 51072..51840, sbhh 51840..52608,
//                sx 52608..52864 (2 x [i=32][4])
__global__ void __launch_bounds__(512, 1)
enc_kernel(const float* __restrict__ X, const float* __restrict__ Wih,
           const float* __restrict__ bih, const float* __restrict__ bhh) {
    extern __shared__ float sm[];
    float* sW   = sm;
    float* sWih = sm + 24704;
    float* sh   = sm + 50048;
    float* sbih = sm + 51072;
    float* sbhh = sm + 51840;
    float* sx   = sm + 52608;
    int tid = threadIdx.x;
    int half = tid >> 8;       // 0: batch rows 0-1, 1: rows 2-3 (within CTA)
    int tl = tid & 255;        // hidden/gate index
    int b0 = blockIdx.x * 4;

#pragma unroll
    for (int s = 0; s < 12; s++) {   // W_ih_enc [768][32] -> smem [j][i] pad 33
        int fidx = tid + 512 * s;    // 0..6143 float4
        int j = fidx >> 3, iq = fidx & 7;
        float4 v = *reinterpret_cast<const float4*>(Wih + j * 32 + iq * 4);
        float* d = sWih + j * 33 + iq * 4;
        d[0] = v.x; d[1] = v.y; d[2] = v.z; d[3] = v.w;
    }
    for (int idx = tid; idx < 768; idx += 512) { sbih[idx] = bih[idx]; sbhh[idx] = bhh[idx]; }
    for (int idx = tid; idx < 1024; idx += 512) sh[idx] = 0.0f;
    if (tid < 128) { int b = tid >> 5, i = tid & 31; sx[i * 4 + b] = X[((b0 + b) * TSEQ + 0) * NP + i]; }
    __syncthreads();
    load_slice16(g_WtEnc, sW, 0, tid);
    __syncthreads();
    int cur = 0;
    float bi0 = sbih[tl], bi1 = sbih[tl + 256], bi2 = sbih[tl + 512];
    float bh0 = sbhh[tl], bh1 = sbhh[tl + 256], bh2 = sbhh[tl + 512];

    for (int t = 0; t < 10; t++) {
        // fused accs for r,z gates; separate proj acc for n gate
        ull a0 = pk2(bi0 + bh0), a1 = pk2(bi1 + bh1), a2 = pk2(bh2), g2 = pk2(bi2);
        const float* sxc = sx + (t & 1) * 128;
        const float* w0p = sWih + tl * 33;
        const float* w1p = sWih + (tl + 256) * 33;
        const float* w2p = sWih + (tl + 512) * 33;
#pragma unroll
        for (int i = 0; i < 32; i++) {
            ull x2 = *reinterpret_cast<const ull*>(sxc + i * 4 + half * 2);
            FMA2(a0, pk2(w0p[i]), x2);
            FMA2(a1, pk2(w1p[i]), x2);
            FMA2(g2, pk2(w2p[i]), x2);
        }
        // prefetch next x into the other buffer (no hazard; readers are behind barriers)
        if (t < 9 && tid < 128) {
            int b = tid >> 5, i = tid & 31;
            sx[((t + 1) & 1) * 128 + i * 4 + b] = X[((b0 + b) * TSEQ + (t + 1)) * NP + i];
        }

        for (int ks = 0; ks < 16; ks++) {
            load_slice16(g_WtEnc, sW + (cur ^ 1) * 12352, (ks + 1) & 15, tid);
            const float* base = sW + cur * 12352;
#pragma unroll
            for (int kl = 0; kl < 16; kl++) {
                const float* wr = base + kl * 772;
                ull w0 = pk2(wr[tl]), w1 = pk2(wr[tl + 256]), w2 = pk2(wr[tl + 512]);
                ull h2 = *reinterpret_cast<const ull*>(sh + (ks * 16 + kl) * 4 + half * 2);
                FMA2(a0, w0, h2); FMA2(a1, w1, h2); FMA2(a2, w2, h2);
            }
            __syncthreads();
            cur ^= 1;
        }
        float a0x, a0y, a1x, a1y, a2x, a2y, g2x, g2y;
        upk(a0, a0x, a0y); upk(a1, a1x, a1y); upk(a2, a2x, a2y); upk(g2, g2x, g2y);
        int bs = half * 2;
        {
            float r = sigm(a0x), z = sigm(a1x);
            float n = tanhf(g2x + r * a2x);
            sh[tl * 4 + bs] = (1.0f - z) * n + z * sh[tl * 4 + bs];
        }
        {
            float r = sigm(a0y), z = sigm(a1y);
            float n = tanhf(g2y + r * a2y);
            sh[tl * 4 + bs + 1] = (1.0f - z) * n + z * sh[tl * 4 + bs + 1];
        }
        __syncthreads();
    }
    g_henc[(b0 + half * 2 + 0) * NH + tl] = sh[tl * 4 + half * 2 + 0];
    g_henc[(b0 + half * 2 + 1) * NH + tl] = sh[tl * 4 + half * 2 + 1];
}

// ======================= latent: mu / log_var / z (coalesced via transposed fc weights) ==========
__global__ void __launch_bounds__(256)
lat_kernel(const float* __restrict__ eps, const float* __restrict__ mb,
           const float* __restrict__ sb_, float* __restrict__ out) {
    __shared__ float hh[NH];
    int b = blockIdx.x, tid = threadIdx.x;
    hh[tid] = g_henc[b * NH + tid];
    __syncthreads();
    float am = mb[tid], as = sb_[tid];
    const float* mT = g_mwT + tid;
    const float* sT = g_swT + tid;
#pragma unroll 8
    for (int k = 0; k < NH; k++) {
        float h = hh[k];
        am += mT[k * NH] * h;   // coalesced: consecutive tid -> consecutive addresses
        as += sT[k * NH] * h;
    }
    out[126976 + b * NH + tid] = am;   // mu
    out[110592 + b * NH + tid] = as;   // log_var
    g_z[b * NH + tid] = am + expf(0.5f * as) * eps[b * NH + tid];
}

// ======================= decoder input projection (batched GEMM, K=32) =======================
__global__ void __launch_bounds__(256, 1)
gi_kernel(const float* __restrict__ X, const float* __restrict__ Wih_all,
          const float* __restrict__ bih_all) {
    extern __shared__ float sm[];
    float* sWih = sm;          // 768*33 = 25344
    float* sxT  = sm + 25344;  // [i=32][66]
    int tid = threadIdx.x;
    int t = blockIdx.x, p = blockIdx.y;
    const float* Wih = Wih_all + p * NG * NP;
#pragma unroll
    for (int s = 0; s < 24; s++) {
        int fidx = tid + 256 * s;
        int j = fidx >> 3, iq = fidx & 7;
        float4 v = *reinterpret_cast<const float4*>(Wih + j * 32 + iq * 4);
        float* d = sWih + j * 33 + iq * 4;
        d[0] = v.x; d[1] = v.y; d[2] = v.z; d[3] = v.w;
    }
    for (int idx = tid; idx < 2048; idx += 256) {
        int b = idx >> 5, i = idx & 31;
        sxT[i * 66 + b] = (t == 0) ? 0.0f : X[(b * TSEQ + 9 + t) * NP + i];
    }
    float bi0 = bih_all[p * NG + tid];
    float bi1 = bih_all[p * NG + 256 + tid];
    float bi2 = bih_all[p * NG + 512 + tid];
    __syncthreads();
    float* og = g_gi + ((size_t)(p * TDEC + t) * NB) * NG;
    for (int bg = 0; bg < 4; bg++) {
        ull a0[8], a1[8], a2[8];
#pragma unroll
        for (int g = 0; g < 8; g++) { a0[g] = pk2(bi0); a1[g] = pk2(bi1); a2[g] = pk2(bi2); }
#pragma unroll
        for (int i = 0; i < 32; i++) {
            ull w0 = pk2(sWih[tid * 33 + i]);
            ull w1 = pk2(sWih[(tid + 256) * 33 + i]);
            ull w2 = pk2(sWih[(tid + 512) * 33 + i]);
            const ull* xp = reinterpret_cast<const ull*>(sxT + i * 66 + bg * 16);
#pragma unroll
            for (int g = 0; g < 8; g++) {
                ull x2 = xp[g];
                FMA2(a0[g], w0, x2); FMA2(a1[g], w1, x2); FMA2(a2[g], w2, x2);
            }
        }
#pragma unroll
        for (int g = 0; g < 8; g++) {
            float x0, x1;
            int b = bg * 16 + 2 * g;
            upk(a0[g], x0, x1); og[(size_t)b * NG + tid] = x0;       og[(size_t)(b + 1) * NG + tid] = x1;
            upk(a1[g], x0, x1); og[(size_t)b * NG + 256 + tid] = x0; og[(size_t)(b + 1) * NG + 256 + tid] = x1;
            upk(a2[g], x0, x1); og[(size_t)b * NG + 512 + tid] = x0; og[(size_t)(b + 1) * NG + 512 + tid] = x1;
        }
    }
}

// ======================= decoder GRU: 128 CTAs = 32 series x 4 batch-chunks, 512 thr =======================
__global__ void __launch_bounds__(512, 1)
dec_kernel(const float* __restrict__ bhh_all,
           const float* __restrict__ lw_all, const float* __restrict__ lb_all,
           float* __restrict__ out) {
    extern __shared__ float sm[];
    float* sW   = sm;           // 2 * 32 * 772 = 49408 (double-buffered 32-k slices of Wt)
    float* sh   = sm + 49408;   // [k=256][20] : cols 0..15 = batch rows, 16B-aligned pairs
    float* sbhh = sm + 54528;   // 768
    float* slw  = sm + 55296;   // 256
    int tid = threadIdx.x;
    int half = tid >> 8;        // 0: batch rows 0-7, 1: rows 8-15
    int tl = tid & 255;         // gate-row index base
    int p = blockIdx.y, c = blockIdx.x, b0 = c * 16;
    const float* Wt = g_Wt + (size_t)p * NH * NG;
    for (int idx = tid; idx < 768; idx += 512) sbhh[idx] = bhh_all[p * NG + idx];
    if (tid < 256) slw[tid] = lw_all[p * NH + tid];
    float lb = lb_all[p];
    for (int idx = tid; idx < 4096; idx += 512) {
        int b = idx >> 8, k = idx & 255;
        sh[k * 20 + b] = g_z[(b0 + b) * NH + k];
    }
    __syncthreads();
    load_slice32(Wt, sW, 0, tid);
    __syncthreads();
    int cur = 0;
    float bh0 = sbhh[tl], bh1 = sbhh[tl + 256], bh2 = sbhh[tl + 512];
    int w = tid >> 5, lane = tid & 31;

    for (int t = 0; t < TDEC; t++) {
        // ---- prefetch this step's gi (24 scalar, coalesced across tl) BEFORE the FMA loop ----
        const float* gip = g_gi + (((size_t)(p * TDEC + t) * NB) + b0 + half * 8) * NG + tl;
        float pg[24];
#pragma unroll
        for (int b = 0; b < 8; b++) {
            pg[b * 3 + 0] = gip[(size_t)b * NG];
            pg[b * 3 + 1] = gip[(size_t)b * NG + 256];
            pg[b * 3 + 2] = gip[(size_t)b * NG + 512];
        }

        ull a0[4], a1[4], a2[4];
#pragma unroll
        for (int g = 0; g < 4; g++) { a0[g] = pk2(bh0); a1[g] = pk2(bh1); a2[g] = pk2(bh2); }

        for (int ks = 0; ks < 8; ks++) {
            load_slice32(Wt, sW + (cur ^ 1) * 24704, (ks + 1) & 7, tid);
            const float* base = sW + cur * 24704;
#pragma unroll
            for (int kl = 0; kl < 32; kl++) {
                const float* wr = base + kl * 772;
                ull w0 = pk2(wr[tl]), w1 = pk2(wr[tl + 256]), w2 = pk2(wr[tl + 512]);
                const ulonglong2* hp = reinterpret_cast<const ulonglong2*>(
                    sh + (ks * 32 + kl) * 20 + half * 8);
                ulonglong2 hA = hp[0];
                ulonglong2 hB = hp[1];
                FMA2(a0[0], w0, hA.x); FMA2(a0[1], w0, hA.y);
                FMA2(a0[2], w0, hB.x); FMA2(a0[3], w0, hB.y);
                FMA2(a1[0], w1, hA.x); FMA2(a1[1], w1, hA.y);
                FMA2(a1[2], w1, hB.x); FMA2(a1[3], w1, hB.y);
                FMA2(a2[0], w2, hA.x); FMA2(a2[1], w2, hA.y);
                FMA2(a2[2], w2, hB.x); FMA2(a2[3], w2, hB.y);
            }
            __syncthreads();
            cur ^= 1;
        }
        // gates + h update: thread owns gate row tl for batch rows half*8 .. half*8+7
#pragma unroll
        for (int g = 0; g < 4; g++) {
            float a0x, a0y, a1x, a1y, a2x, a2y;
            upk(a0[g], a0x, a0y); upk(a1[g], a1x, a1y); upk(a2[g], a2x, a2y);
            int b = 2 * g;                 // local (within this half) batch row
            int bs = half * 8 + b;         // row within chunk
            {
                float r = sigm(pg[b * 3 + 0] + a0x), z = sigm(pg[b * 3 + 1] + a1x);
                float n = tanhf(pg[b * 3 + 2] + r * a2x);
                sh[tl * 20 + bs] = (1.0f - z) * n + z * sh[tl * 20 + bs];
            }
            {
                float r = sigm(pg[(b + 1) * 3 + 0] + a0y), z = sigm(pg[(b + 1) * 3 + 1] + a1y);
                float n = tanhf(pg[(b + 1) * 3 + 2] + r * a2y);
                sh[tl * 20 + bs + 1] = (1.0f - z) * n + z * sh[tl * 20 + bs + 1];
            }
        }
        __syncthreads();
        // linear head: warp w reduces batch row w (16 warps, 16 rows)
        {
            float s = 0.0f;
#pragma unroll
            for (int m = 0; m < 8; m++) { int k = lane + 32 * m; s += slw[k] * sh[k * 20 + w]; }
#pragma unroll
            for (int off = 16; off; off >>= 1) s += __shfl_xor_sync(0xffffffffu, s, off);
            if (lane == 0) out[((size_t)p * NB + b0 + w) * TDEC + t] = s + lb;
        }
    }
}

// ======================= launcher =======================
extern "C" void kernel_launch(void* const* d_in, const int* in_sizes, int n_in,
                              void* d_out, int out_size) {
    const float* X       = (const float*)d_in[0];
    const float* eps     = (const float*)d_in[1];
    const float* Wih_enc = (const float*)d_in[2];
    const float* Whh_enc = (const float*)d_in[3];
    const float* bih_enc = (const float*)d_in[4];
    const float* bhh_enc = (const float*)d_in[5];
    const float* mw      = (const float*)d_in[6];
    const float* mb      = (const float*)d_in[7];
    const float* sw      = (const float*)d_in[8];
    const float* sb      = (const float*)d_in[9];
    const float* Wih_dec = (const float*)d_in[10];
    const float* Whh_dec = (const float*)d_in[11];
    const float* bih_dec = (const float*)d_in[12];
    const float* bhh_dec = (const float*)d_in[13];
    const float* lw      = (const float*)d_in[14];
    const float* lbv     = (const float*)d_in[15];
    float* out = (float*)d_out;

    int smem_enc = 52864 * 4;              // 211,456 B
    int smem_gi  = (25344 + 32 * 66) * 4;  // 109,824 B
    int smem_dec = 55552 * 4;              // 222,208 B
    cudaFuncSetAttribute(enc_kernel, cudaFuncAttributeMaxDynamicSharedMemorySize, smem_enc);
    cudaFuncSetAttribute(gi_kernel,  cudaFuncAttributeMaxDynamicSharedMemorySize, smem_gi);
    cudaFuncSetAttribute(dec_kernel, cudaFuncAttributeMaxDynamicSharedMemorySize, smem_dec);

    tr_kernel<<<dim3(8, 24, 32), dim3(32, 8)>>>(Whh_dec);
    tr_enc_kernel<<<dim3(8, 24), dim3(32, 8)>>>(Whh_enc);
    trf_kernel<<<dim3(8, 8, 2), dim3(32, 8)>>>(mw, sw);
    gi_kernel<<<dim3(TDEC, NP), 256, smem_gi>>>(X, Wih_dec, bih_dec);
    enc_kernel<<<16, 512, smem_enc>>>(X, Wih_enc, bih_enc, bhh_enc);
    lat_kernel<<<NB, 256>>>(eps, mb, sb, out);
    dec_kernel<<<dim3(4, NP), 512, smem_dec>>>(bhh_dec, lw, lbv, out);
}

// round 11
// speedup vs baseline: 1.8666x; 1.3533x over previous
#include <cuda_runtime.h>
#include <math.h>
#include <stdint.h>

typedef unsigned long long ull;

#define NB 64
#define NH 256
#define NG 768
#define NP 32
#define TSEQ 64
#define TDEC 54

// -------- scratch (device globals; no allocation in kernel_launch) --------
__device__ float g_gi[84934656];   // [P=32][t=54][b=64][j=768] decoder input-proj (incl b_ih)
__device__ float g_z[NB * NH];     // latent z
__device__ float g_henc[NB * NH];  // encoder final hidden
__device__ float g_Wt[32 * 256 * 768];  // W_hh_dec transposed: [p][k=256][j=768]
__device__ float g_WtEnc[256 * 768];    // W_hh_enc transposed: [k=256][j=768]
__device__ float g_mwT[NH * NH];   // fc_mu_w transposed  [k][j]
__device__ float g_swT[NH * NH];   // fc_std_w transposed [k][j]

// -------- f32x2 helpers --------
__device__ __forceinline__ ull pk(float x, float y) {
    ull r; asm("mov.b64 %0, {%1,%2};" : "=l"(r) : "f"(x), "f"(y)); return r;
}
__device__ __forceinline__ ull pk2(float x) { return pk(x, x); }
__device__ __forceinline__ void upk(ull v, float& x, float& y) {
    asm("mov.b64 {%0,%1}, %2;" : "=f"(x), "=f"(y) : "l"(v));
}
#define FMA2(acc, a, b) asm("fma.rn.f32x2 %0, %1, %2, %0;" : "+l"(acc) : "l"(a), "l"(b))

__device__ __forceinline__ float sigm(float x) { return 1.0f / (1.0f + expf(-x)); }

// -------- mbarrier + bulk-copy helpers --------
__device__ __forceinline__ uint32_t smem_u32(const void* p) {
    uint32_t a;
    asm("{ .reg .u64 t; cvta.to.shared.u64 t, %1; cvt.u32.u64 %0, t; }" : "=r"(a) : "l"(p));
    return a;
}
__device__ __forceinline__ void mbar_init(uint32_t mbar, uint32_t cnt) {
    asm volatile("mbarrier.init.shared.b64 [%0], %1;" :: "r"(mbar), "r"(cnt) : "memory");
}
__device__ __forceinline__ void mbar_expect(uint32_t mbar, uint32_t bytes) {
    asm volatile("mbarrier.arrive.expect_tx.shared.b64 _, [%0], %1;" :: "r"(mbar), "r"(bytes) : "memory");
}
__device__ __forceinline__ void bulk_cp(uint32_t dst, const float* src, uint32_t bytes, uint32_t mbar) {
    asm volatile(
        "cp.async.bulk.shared::cluster.global.mbarrier::complete_tx::bytes [%0], [%1], %2, [%3];"
        :: "r"(dst), "l"(src), "r"(bytes), "r"(mbar) : "memory");
}
__device__ __forceinline__ void mbar_wait(uint32_t mbar, uint32_t parity) {
    asm volatile(
        "{\n\t.reg .pred P1;\n\t"
        "WAIT_%=:\n\t"
        "mbarrier.try_wait.parity.acquire.cta.shared::cta.b64 P1, [%0], %1, 0x989680;\n\t"
        "@P1 bra.uni DONE_%=;\n\t"
        "bra.uni WAIT_%=;\n\t"
        "DONE_%=:\n\t}"
        :: "r"(mbar), "r"(parity) : "memory");
}

// ======================= W_hh_dec transpose: [p][768][256] -> [p][256][768] =======================
__global__ void tr_kernel(const float* __restrict__ W) {
    __shared__ float tile[32][33];
    int p = blockIdx.z;
    int k0 = blockIdx.x * 32, j0 = blockIdx.y * 32;
    const float* Wp = W + (size_t)p * NG * NH;
    float* Wtp = g_Wt + (size_t)p * NH * NG;
    int x = threadIdx.x, y0 = threadIdx.y;   // block (32, 8)
#pragma unroll
    for (int dy = 0; dy < 32; dy += 8) {
        int j = j0 + y0 + dy;
        tile[y0 + dy][x] = Wp[(size_t)j * NH + k0 + x];
    }
    __syncthreads();
#pragma unroll
    for (int dy = 0; dy < 32; dy += 8) {
        int k = k0 + y0 + dy;
        Wtp[(size_t)k * NG + j0 + x] = tile[x][y0 + dy];
    }
}

// ======================= W_hh_enc transpose: [768][256] -> [256][768] =======================
__global__ void tr_enc_kernel(const float* __restrict__ W) {
    __shared__ float tile[32][33];
    int k0 = blockIdx.x * 32, j0 = blockIdx.y * 32;
    int x = threadIdx.x, y0 = threadIdx.y;   // block (32, 8)
#pragma unroll
    for (int dy = 0; dy < 32; dy += 8) {
        int j = j0 + y0 + dy;
        tile[y0 + dy][x] = W[j * NH + k0 + x];
    }
    __syncthreads();
#pragma unroll
    for (int dy = 0; dy < 32; dy += 8) {
        int k = k0 + y0 + dy;
        g_WtEnc[k * NG + j0 + x] = tile[x][y0 + dy];
    }
}

// ======================= fc weight transpose: [256][256] -> [256][256]^T (x2 matrices) ==========
__global__ void trf_kernel(const float* __restrict__ mw, const float* __restrict__ sw_) {
    __shared__ float tile[32][33];
    int sel = blockIdx.z;
    const float* Wp = sel ? sw_ : mw;
    float* Wtp = sel ? g_swT : g_mwT;
    int k0 = blockIdx.x * 32, j0 = blockIdx.y * 32;
    int x = threadIdx.x, y0 = threadIdx.y;   // block (32, 8)
#pragma unroll
    for (int dy = 0; dy < 32; dy += 8) {
        int j = j0 + y0 + dy;
        tile[y0 + dy][x] = Wp[j * NH + k0 + x];
    }
    __syncthreads();
#pragma unroll
    for (int dy = 0; dy < 32; dy += 8) {
        int k = k0 + y0 + dy;
        Wtp[k * NH + j0 + x] = tile[x][y0 + dy];
    }
}

// ======================= encoder GRU: 16 CTAs x 4 batch rows, 512 threads =======================
// smem (floats): sW 0..24576 (2 x [16][768] slices), sWih 24576..49920 ([768][33]),
//                sh 49920..50944 ([k=256][4]), sbih 50944..51712, sbhh 51712..52480,
//                sx 52480..52736 (2 x [i=32][4]), mbar 52736..52740
#define ENC_SLICE_FLOATS (16 * 768)
#define ENC_SLICE_BYTES  (ENC_SLICE_FLOATS * 4)
__global__ void __launch_bounds__(512, 1)
enc_kernel(const float* __restrict__ X, const float* __restrict__ Wih,
           const float* __restrict__ bih, const float* __restrict__ bhh) {
    extern __shared__ float sm[];
    float* sW   = sm;
    float* sWih = sm + 24576;
    float* sh   = sm + 49920;
    float* sbih = sm + 50944;
    float* sbhh = sm + 51712;
    float* sx   = sm + 52480;
    float* smb  = sm + 52736;
    int tid = threadIdx.x;
    int half = tid >> 8;       // 0: batch rows 0-1, 1: rows 2-3 (within CTA)
    int tl = tid & 255;        // hidden/gate index
    int b0 = blockIdx.x * 4;
    uint32_t mb0 = smem_u32(smb), mb1 = mb0 + 8;
    uint32_t sWa = smem_u32(sW);

#pragma unroll
    for (int s = 0; s < 12; s++) {   // W_ih_enc [768][32] -> smem [j][i] pad 33
        int fidx = tid + 512 * s;    // 0..6143 float4
        int j = fidx >> 3, iq = fidx & 7;
        float4 v = *reinterpret_cast<const float4*>(Wih + j * 32 + iq * 4);
        float* d = sWih + j * 33 + iq * 4;
        d[0] = v.x; d[1] = v.y; d[2] = v.z; d[3] = v.w;
    }
    for (int idx = tid; idx < 768; idx += 512) { sbih[idx] = bih[idx]; sbhh[idx] = bhh[idx]; }
    for (int idx = tid; idx < 1024; idx += 512) sh[idx] = 0.0f;
    if (tid < 128) { int b = tid >> 5, i = tid & 31; sx[i * 4 + b] = X[((b0 + b) * TSEQ + 0) * NP + i]; }
    if (tid == 0) { mbar_init(mb0, 1); mbar_init(mb1, 1); }
    __syncthreads();
    if (tid == 0) {
        mbar_expect(mb0, ENC_SLICE_BYTES);
        bulk_cp(sWa, g_WtEnc, ENC_SLICE_BYTES, mb0);
        mbar_expect(mb1, ENC_SLICE_BYTES);
        bulk_cp(sWa + ENC_SLICE_BYTES, g_WtEnc + ENC_SLICE_FLOATS, ENC_SLICE_BYTES, mb1);
    }
    int ph0 = 0, ph1 = 0, sl = 0;
    const int NSL = 10 * 16;
    float bi0 = sbih[tl], bi1 = sbih[tl + 256], bi2 = sbih[tl + 512];
    float bh0 = sbhh[tl], bh1 = sbhh[tl + 256], bh2 = sbhh[tl + 512];

    for (int t = 0; t < 10; t++) {
        // fused accs for r,z gates; separate proj acc for n gate
        ull a0 = pk2(bi0 + bh0), a1 = pk2(bi1 + bh1), a2 = pk2(bh2), g2 = pk2(bi2);
        const float* sxc = sx + (t & 1) * 128;
        const float* w0p = sWih + tl * 33;
        const float* w1p = sWih + (tl + 256) * 33;
        const float* w2p = sWih + (tl + 512) * 33;
#pragma unroll
        for (int i = 0; i < 32; i++) {
            ull x2 = *reinterpret_cast<const ull*>(sxc + i * 4 + half * 2);
            FMA2(a0, pk2(w0p[i]), x2);
            FMA2(a1, pk2(w1p[i]), x2);
            FMA2(g2, pk2(w2p[i]), x2);
        }
        // prefetch next x into the other buffer
        if (t < 9 && tid < 128) {
            int b = tid >> 5, i = tid & 31;
            sx[((t + 1) & 1) * 128 + i * 4 + b] = X[((b0 + b) * TSEQ + (t + 1)) * NP + i];
        }

        for (int ks = 0; ks < 16; ks++) {
            int cur = sl & 1;
            if (cur == 0) { mbar_wait(mb0, ph0); ph0 ^= 1; }
            else          { mbar_wait(mb1, ph1); ph1 ^= 1; }
            const float* base = sW + cur * ENC_SLICE_FLOATS;
#pragma unroll
            for (int kl = 0; kl < 16; kl++) {
                const float* wr = base + kl * 768;
                ull w0 = pk2(wr[tl]), w1 = pk2(wr[tl + 256]), w2 = pk2(wr[tl + 512]);
                ull h2 = *reinterpret_cast<const ull*>(sh + (ks * 16 + kl) * 4 + half * 2);
                FMA2(a0, w0, h2); FMA2(a1, w1, h2); FMA2(a2, w2, h2);
            }
            __syncthreads();
            if (tid == 0 && sl + 2 < NSL) {
                uint32_t mb = cur ? mb1 : mb0;
                mbar_expect(mb, ENC_SLICE_BYTES);
                bulk_cp(sWa + cur * ENC_SLICE_BYTES,
                        g_WtEnc + (size_t)((sl + 2) & 15) * ENC_SLICE_FLOATS,
                        ENC_SLICE_BYTES, mb);
            }
            sl++;
        }
        float a0x, a0y, a1x, a1y, a2x, a2y, g2x, g2y;
        upk(a0, a0x, a0y); upk(a1, a1x, a1y); upk(a2, a2x, a2y); upk(g2, g2x, g2y);
        int bs = half * 2;
        {
            float r = sigm(a0x), z = sigm(a1x);
            float n = tanhf(g2x + r * a2x);
            sh[tl * 4 + bs] = (1.0f - z) * n + z * sh[tl * 4 + bs];
        }
        {
            float r = sigm(a0y), z = sigm(a1y);
            float n = tanhf(g2y + r * a2y);
            sh[tl * 4 + bs + 1] = (1.0f - z) * n + z * sh[tl * 4 + bs + 1];
        }
        __syncthreads();
    }
    g_henc[(b0 + half * 2 + 0) * NH + tl] = sh[tl * 4 + half * 2 + 0];
    g_henc[(b0 + half * 2 + 1) * NH + tl] = sh[tl * 4 + half * 2 + 1];
}

// ======================= latent: mu / log_var / z (coalesced via transposed fc weights) ==========
__global__ void __launch_bounds__(256)
lat_kernel(const float* __restrict__ eps, const float* __restrict__ mb,
           const float* __restrict__ sb_, float* __restrict__ out) {
    __shared__ float hh[NH];
    int b = blockIdx.x, tid = threadIdx.x;
    hh[tid] = g_henc[b * NH + tid];
    __syncthreads();
    float am = mb[tid], as = sb_[tid];
    const float* mT = g_mwT + tid;
    const float* sT = g_swT + tid;
#pragma unroll 8
    for (int k = 0; k < NH; k++) {
        float h = hh[k];
        am += mT[k * NH] * h;
        as += sT[k * NH] * h;
    }
    out[126976 + b * NH + tid] = am;   // mu
    out[110592 + b * NH + tid] = as;   // log_var
    g_z[b * NH + tid] = am + expf(0.5f * as) * eps[b * NH + tid];
}

// ======================= decoder input projection (batched GEMM, K=32) =======================
__global__ void __launch_bounds__(256, 1)
gi_kernel(const float* __restrict__ X, const float* __restrict__ Wih_all,
          const float* __restrict__ bih_all) {
    extern __shared__ float sm[];
    float* sWih = sm;          // 768*33 = 25344
    float* sxT  = sm + 25344;  // [i=32][66]
    int tid = threadIdx.x;
    int t = blockIdx.x, p = blockIdx.y;
    const float* Wih = Wih_all + p * NG * NP;
#pragma unroll
    for (int s = 0; s < 24; s++) {
        int fidx = tid + 256 * s;
        int j = fidx >> 3, iq = fidx & 7;
        float4 v = *reinterpret_cast<const float4*>(Wih + j * 32 + iq * 4);
        float* d = sWih + j * 33 + iq * 4;
        d[0] = v.x; d[1] = v.y; d[2] = v.z; d[3] = v.w;
    }
    for (int idx = tid; idx < 2048; idx += 256) {
        int b = idx >> 5, i = idx & 31;
        sxT[i * 66 + b] = (t == 0) ? 0.0f : X[(b * TSEQ + 9 + t) * NP + i];
    }
    float bi0 = bih_all[p * NG + tid];
    float bi1 = bih_all[p * NG + 256 + tid];
    float bi2 = bih_all[p * NG + 512 + tid];
    __syncthreads();
    float* og = g_gi + ((size_t)(p * TDEC + t) * NB) * NG;
    for (int bg = 0; bg < 4; bg++) {
        ull a0[8], a1[8], a2[8];
#pragma unroll
        for (int g = 0; g < 8; g++) { a0[g] = pk2(bi0); a1[g] = pk2(bi1); a2[g] = pk2(bi2); }
#pragma unroll
        for (int i = 0; i < 32; i++) {
            ull w0 = pk2(sWih[tid * 33 + i]);
            ull w1 = pk2(sWih[(tid + 256) * 33 + i]);
            ull w2 = pk2(sWih[(tid + 512) * 33 + i]);
            const ull* xp = reinterpret_cast<const ull*>(sxT + i * 66 + bg * 16);
#pragma unroll
            for (int g = 0; g < 8; g++) {
                ull x2 = xp[g];
                FMA2(a0[g], w0, x2); FMA2(a1[g], w1, x2); FMA2(a2[g], w2, x2);
            }
        }
#pragma unroll
        for (int g = 0; g < 8; g++) {
            float x0, x1;
            int b = bg * 16 + 2 * g;
            upk(a0[g], x0, x1); og[(size_t)b * NG + tid] = x0;       og[(size_t)(b + 1) * NG + tid] = x1;
            upk(a1[g], x0, x1); og[(size_t)b * NG + 256 + tid] = x0; og[(size_t)(b + 1) * NG + 256 + tid] = x1;
            upk(a2[g], x0, x1); og[(size_t)b * NG + 512 + tid] = x0; og[(size_t)(b + 1) * NG + 512 + tid] = x1;
        }
    }
}

// ======================= decoder GRU: 128 CTAs = 32 series x 4 batch-chunks, 512 thr =======================
// smem (floats): sW 0..49152 (2 x [32][768] slices), sh 49152..54272 ([k=256][20]),
//                sbhh 54272..55040, slw 55040..55296, mbar 55296..55300
#define DEC_SLICE_FLOATS (32 * 768)
#define DEC_SLICE_BYTES  (DEC_SLICE_FLOATS * 4)
__global__ void __launch_bounds__(512, 1)
dec_kernel(const float* __restrict__ bhh_all,
           const float* __restrict__ lw_all, const float* __restrict__ lb_all,
           float* __restrict__ out) {
    extern __shared__ float sm[];
    float* sW   = sm;
    float* sh   = sm + 49152;
    float* sbhh = sm + 54272;
    float* slw  = sm + 55040;
    float* smb  = sm + 55296;
    int tid = threadIdx.x;
    int half = tid >> 8;        // 0: batch rows 0-7, 1: rows 8-15
    int tl = tid & 255;         // gate-row index base
    int p = blockIdx.y, c = blockIdx.x, b0 = c * 16;
    const float* Wt = g_Wt + (size_t)p * NH * NG;
    uint32_t mb0 = smem_u32(smb), mb1 = mb0 + 8;
    uint32_t sWa = smem_u32(sW);
    for (int idx = tid; idx < 768; idx += 512) sbhh[idx] = bhh_all[p * NG + idx];
    if (tid < 256) slw[tid] = lw_all[p * NH + tid];
    float lb = lb_all[p];
    for (int idx = tid; idx < 4096; idx += 512) {
        int b = idx >> 8, k = idx & 255;
        sh[k * 20 + b] = g_z[(b0 + b) * NH + k];
    }
    if (tid == 0) { mbar_init(mb0, 1); mbar_init(mb1, 1); }
    __syncthreads();
    if (tid == 0) {
        mbar_expect(mb0, DEC_SLICE_BYTES);
        bulk_cp(sWa, Wt, DEC_SLICE_BYTES, mb0);
        mbar_expect(mb1, DEC_SLICE_BYTES);
        bulk_cp(sWa + DEC_SLICE_BYTES, Wt + DEC_SLICE_FLOATS, DEC_SLICE_BYTES, mb1);
    }
    int ph0 = 0, ph1 = 0, sl = 0;
    const int NSL = TDEC * 8;
    float bh0 = sbhh[tl], bh1 = sbhh[tl + 256], bh2 = sbhh[tl + 512];
    int w = tid >> 5, lane = tid & 31;

    for (int t = 0; t < TDEC; t++) {
        // ---- prefetch this step's gi (24 scalar, coalesced across tl) BEFORE the FMA loop ----
        const float* gip = g_gi + (((size_t)(p * TDEC + t) * NB) + b0 + half * 8) * NG + tl;
        float pg[24];
#pragma unroll
        for (int b = 0; b < 8; b++) {
            pg[b * 3 + 0] = gip[(size_t)b * NG];
            pg[b * 3 + 1] = gip[(size_t)b * NG + 256];
            pg[b * 3 + 2] = gip[(size_t)b * NG + 512];
        }

        ull a0[4], a1[4], a2[4];
#pragma unroll
        for (int g = 0; g < 4; g++) { a0[g] = pk2(bh0); a1[g] = pk2(bh1); a2[g] = pk2(bh2); }

        for (int ks = 0; ks < 8; ks++) {
            int cur = sl & 1;
            if (cur == 0) { mbar_wait(mb0, ph0); ph0 ^= 1; }
            else          { mbar_wait(mb1, ph1); ph1 ^= 1; }
            const float* base = sW + cur * DEC_SLICE_FLOATS;
#pragma unroll
            for (int kl = 0; kl < 32; kl++) {
                const float* wr = base + kl * 768;
                ull w0 = pk2(wr[tl]), w1 = pk2(wr[tl + 256]), w2 = pk2(wr[tl + 512]);
                const ulonglong2* hp = reinterpret_cast<const ulonglong2*>(
                    sh + (ks * 32 + kl) * 20 + half * 8);
                ulonglong2 hA = hp[0];
                ulonglong2 hB = hp[1];
                FMA2(a0[0], w0, hA.x); FMA2(a0[1], w0, hA.y);
                FMA2(a0[2], w0, hB.x); FMA2(a0[3], w0, hB.y);
                FMA2(a1[0], w1, hA.x); FMA2(a1[1], w1, hA.y);
                FMA2(a1[2], w1, hB.x); FMA2(a1[3], w1, hB.y);
                FMA2(a2[0], w2, hA.x); FMA2(a2[1], w2, hA.y);
                FMA2(a2[2], w2, hB.x); FMA2(a2[3], w2, hB.y);
            }
            __syncthreads();
            if (tid == 0 && sl + 2 < NSL) {
                uint32_t mb = cur ? mb1 : mb0;
                mbar_expect(mb, DEC_SLICE_BYTES);
                bulk_cp(sWa + cur * DEC_SLICE_BYTES,
                        Wt + (size_t)((sl + 2) & 7) * DEC_SLICE_FLOATS,
                        DEC_SLICE_BYTES, mb);
            }
            sl++;
        }
        // gates + h update: thread owns gate row tl for batch rows half*8 .. half*8+7
#pragma unroll
        for (int g = 0; g < 4; g++) {
            float a0x, a0y, a1x, a1y, a2x, a2y;
            upk(a0[g], a0x, a0y); upk(a1[g], a1x, a1y); upk(a2[g], a2x, a2y);
            int b = 2 * g;
            int bs = half * 8 + b;
            {
                float r = sigm(pg[b * 3 + 0] + a0x), z = sigm(pg[b * 3 + 1] + a1x);
                float n = tanhf(pg[b * 3 + 2] + r * a2x);
                sh[tl * 20 + bs] = (1.0f - z) * n + z * sh[tl * 20 + bs];
            }
            {
                float r = sigm(pg[(b + 1) * 3 + 0] + a0y), z = sigm(pg[(b + 1) * 3 + 1] + a1y);
                float n = tanhf(pg[(b + 1) * 3 + 2] + r * a2y);
                sh[tl * 20 + bs + 1] = (1.0f - z) * n + z * sh[tl * 20 + bs + 1];
            }
        }
        __syncthreads();
        // linear head: warp w reduces batch row w (16 warps, 16 rows)
        {
            float s = 0.0f;
#pragma unroll
            for (int m = 0; m < 8; m++) { int k = lane + 32 * m; s += slw[k] * sh[k * 20 + w]; }
#pragma unroll
            for (int off = 16; off; off >>= 1) s += __shfl_xor_sync(0xffffffffu, s, off);
            if (lane == 0) out[((size_t)p * NB + b0 + w) * TDEC + t] = s + lb;
        }
    }
}

// ======================= launcher =======================
extern "C" void kernel_launch(void* const* d_in, const int* in_sizes, int n_in,
                              void* d_out, int out_size) {
    const float* X       = (const float*)d_in[0];
    const float* eps     = (const float*)d_in[1];
    const float* Wih_enc = (const float*)d_in[2];
    const float* Whh_enc = (const float*)d_in[3];
    const float* bih_enc = (const float*)d_in[4];
    const float* bhh_enc = (const float*)d_in[5];
    const float* mw      = (const float*)d_in[6];
    const float* mb      = (const float*)d_in[7];
    const float* sw      = (const float*)d_in[8];
    const float* sb      = (const float*)d_in[9];
    const float* Wih_dec = (const float*)d_in[10];
    const float* Whh_dec = (const float*)d_in[11];
    const float* bih_dec = (const float*)d_in[12];
    const float* bhh_dec = (const float*)d_in[13];
    const float* lw      = (const float*)d_in[14];
    const float* lbv     = (const float*)d_in[15];
    float* out = (float*)d_out;

    int smem_enc = 52740 * 4;              // 210,960 B
    int smem_gi  = (25344 + 32 * 66) * 4;  // 109,824 B
    int smem_dec = 55300 * 4;              // 221,200 B
    cudaFuncSetAttribute(enc_kernel, cudaFuncAttributeMaxDynamicSharedMemorySize, smem_enc);
    cudaFuncSetAttribute(gi_kernel,  cudaFuncAttributeMaxDynamicSharedMemorySize, smem_gi);
    cudaFuncSetAttribute(dec_kernel, cudaFuncAttributeMaxDynamicSharedMemorySize, smem_dec);

    tr_kernel<<<dim3(8, 24, 32), dim3(32, 8)>>>(Whh_dec);
    tr_enc_kernel<<<dim3(8, 24), dim3(32, 8)>>>(Whh_enc);
    trf_kernel<<<dim3(8, 8, 2), dim3(32, 8)>>>(mw, sw);
    gi_kernel<<<dim3(TDEC, NP), 256, smem_gi>>>(X, Wih_dec, bih_dec);
    enc_kernel<<<16, 512, smem_enc>>>(X, Wih_enc, bih_enc, bhh_enc);
    lat_kernel<<<NB, 256>>>(eps, mb, sb, out);
    dec_kernel<<<dim3(4, NP), 512, smem_dec>>>(bhh_dec, lw, lbv, out);
}

// round 12
// speedup vs baseline: 1.8707x; 1.0022x over previous
#include <cuda_runtime.h>
#include <math.h>
#include <stdint.h>

typedef unsigned long long ull;

#define NB 64
#define NH 256
#define NG 768
#define NP 32
#define TSEQ 64
#define TDEC 54

// -------- scratch (device globals; no allocation in kernel_launch) --------
__device__ float g_gi[84934656];   // [P=32][t=54][b=64][j=768] decoder input-proj (incl b_ih)
__device__ float g_z[NB * NH];     // latent z
__device__ float g_henc[NB * NH];  // encoder final hidden
__device__ float g_Wt[32 * 256 * 768];  // W_hh_dec transposed: [p][k=256][j=768]
__device__ float g_WtEnc[256 * 768];    // W_hh_enc transposed: [k=256][j=768]
__device__ float g_mwT[NH * NH];   // fc_mu_w transposed  [k][j]
__device__ float g_swT[NH * NH];   // fc_std_w transposed [k][j]

// -------- f32x2 helpers --------
__device__ __forceinline__ ull pk(float x, float y) {
    ull r; asm("mov.b64 %0, {%1,%2};" : "=l"(r) : "f"(x), "f"(y)); return r;
}
__device__ __forceinline__ ull pk2(float x) { return pk(x, x); }
__device__ __forceinline__ void upk(ull v, float& x, float& y) {
    asm("mov.b64 {%0,%1}, %2;" : "=f"(x), "=f"(y) : "l"(v));
}
#define FMA2(acc, a, b) asm("fma.rn.f32x2 %0, %1, %2, %0;" : "+l"(acc) : "l"(a), "l"(b))

__device__ __forceinline__ float sigm(float x) { return 1.0f / (1.0f + expf(-x)); }

// -------- mbarrier + bulk-copy helpers --------
__device__ __forceinline__ uint32_t smem_u32(const void* p) {
    uint32_t a;
    asm("{ .reg .u64 t; cvta.to.shared.u64 t, %1; cvt.u32.u64 %0, t; }" : "=r"(a) : "l"(p));
    return a;
}
__device__ __forceinline__ void mbar_init(uint32_t mbar, uint32_t cnt) {
    asm volatile("mbarrier.init.shared.b64 [%0], %1;" :: "r"(mbar), "r"(cnt) : "memory");
}
__device__ __forceinline__ void mbar_expect(uint32_t mbar, uint32_t bytes) {
    asm volatile("mbarrier.arrive.expect_tx.shared.b64 _, [%0], %1;" :: "r"(mbar), "r"(bytes) : "memory");
}
__device__ __forceinline__ void bulk_cp(uint32_t dst, const float* src, uint32_t bytes, uint32_t mbar) {
    asm volatile(
        "cp.async.bulk.shared::cluster.global.mbarrier::complete_tx::bytes [%0], [%1], %2, [%3];"
        :: "r"(dst), "l"(src), "r"(bytes), "r"(mbar) : "memory");
}
__device__ __forceinline__ void mbar_wait(uint32_t mbar, uint32_t parity) {
    asm volatile(
        "{\n\t.reg .pred P1;\n\t"
        "WAIT_%=:\n\t"
        "mbarrier.try_wait.parity.acquire.cta.shared::cta.b64 P1, [%0], %1, 0x989680;\n\t"
        "@P1 bra.uni DONE_%=;\n\t"
        "bra.uni WAIT_%=;\n\t"
        "DONE_%=:\n\t}"
        :: "r"(mbar), "r"(parity) : "memory");
}

// ======================= W_hh_dec transpose: [p][768][256] -> [p][256][768] =======================
__global__ void tr_kernel(const float* __restrict__ W) {
    __shared__ float tile[32][33];
    int p = blockIdx.z;
    int k0 = blockIdx.x * 32, j0 = blockIdx.y * 32;
    const float* Wp = W + (size_t)p * NG * NH;
    float* Wtp = g_Wt + (size_t)p * NH * NG;
    int x = threadIdx.x, y0 = threadIdx.y;   // block (32, 8)
#pragma unroll
    for (int dy = 0; dy < 32; dy += 8) {
        int j = j0 + y0 + dy;
        tile[y0 + dy][x] = Wp[(size_t)j * NH + k0 + x];
    }
    __syncthreads();
#pragma unroll
    for (int dy = 0; dy < 32; dy += 8) {
        int k = k0 + y0 + dy;
        Wtp[(size_t)k * NG + j0 + x] = tile[x][y0 + dy];
    }
}

// ======================= W_hh_enc transpose: [768][256] -> [256][768] =======================
__global__ void tr_enc_kernel(const float* __restrict__ W) {
    __shared__ float tile[32][33];
    int k0 = blockIdx.x * 32, j0 = blockIdx.y * 32;
    int x = threadIdx.x, y0 = threadIdx.y;   // block (32, 8)
#pragma unroll
    for (int dy = 0; dy < 32; dy += 8) {
        int j = j0 + y0 + dy;
        tile[y0 + dy][x] = W[j * NH + k0 + x];
    }
    __syncthreads();
#pragma unroll
    for (int dy = 0; dy < 32; dy += 8) {
        int k = k0 + y0 + dy;
        g_WtEnc[k * NG + j0 + x] = tile[x][y0 + dy];
    }
}

// ======================= fc weight transpose: [256][256] -> [256][256]^T (x2 matrices) ==========
__global__ void trf_kernel(const float* __restrict__ mw, const float* __restrict__ sw_) {
    __shared__ float tile[32][33];
    int sel = blockIdx.z;
    const float* Wp = sel ? sw_ : mw;
    float* Wtp = sel ? g_swT : g_mwT;
    int k0 = blockIdx.x * 32, j0 = blockIdx.y * 32;
    int x = threadIdx.x, y0 = threadIdx.y;   // block (32, 8)
#pragma unroll
    for (int dy = 0; dy < 32; dy += 8) {
        int j = j0 + y0 + dy;
        tile[y0 + dy][x] = Wp[j * NH + k0 + x];
    }
    __syncthreads();
#pragma unroll
    for (int dy = 0; dy < 32; dy += 8) {
        int k = k0 + y0 + dy;
        Wtp[k * NH + j0 + x] = tile[x][y0 + dy];
    }
}

// ======================= encoder GRU: 16 CTAs x 4 batch rows, 512 threads =======================
// smem (floats): sW 0..24576 (2 x [16][768] slices), sWih 24576..49920 ([768][33]),
//                sh 49920..50944 ([k=256][4]), sbih 50944..51712, sbhh 51712..52480,
//                sx 52480..52736 (2 x [i=32][4]), mbar 52736..52740
#define ENC_SLICE_FLOATS (16 * 768)
#define ENC_SLICE_BYTES  (ENC_SLICE_FLOATS * 4)
__global__ void __launch_bounds__(512, 1)
enc_kernel(const float* __restrict__ X, const float* __restrict__ Wih,
           const float* __restrict__ bih, const float* __restrict__ bhh) {
    extern __shared__ float sm[];
    float* sW   = sm;
    float* sWih = sm + 24576;
    float* sh   = sm + 49920;
    float* sbih = sm + 50944;
    float* sbhh = sm + 51712;
    float* sx   = sm + 52480;
    float* smb  = sm + 52736;
    int tid = threadIdx.x;
    int half = tid >> 8;       // 0: batch rows 0-1, 1: rows 2-3 (within CTA)
    int tl = tid & 255;        // hidden/gate index
    int b0 = blockIdx.x * 4;
    uint32_t mb0 = smem_u32(smb), mb1 = mb0 + 8;
    uint32_t sWa = smem_u32(sW);

#pragma unroll
    for (int s = 0; s < 12; s++) {   // W_ih_enc [768][32] -> smem [j][i] pad 33
        int fidx = tid + 512 * s;    // 0..6143 float4
        int j = fidx >> 3, iq = fidx & 7;
        float4 v = *reinterpret_cast<const float4*>(Wih + j * 32 + iq * 4);
        float* d = sWih + j * 33 + iq * 4;
        d[0] = v.x; d[1] = v.y; d[2] = v.z; d[3] = v.w;
    }
    for (int idx = tid; idx < 768; idx += 512) { sbih[idx] = bih[idx]; sbhh[idx] = bhh[idx]; }
    for (int idx = tid; idx < 1024; idx += 512) sh[idx] = 0.0f;
    if (tid < 128) { int b = tid >> 5, i = tid & 31; sx[i * 4 + b] = X[((b0 + b) * TSEQ + 0) * NP + i]; }
    if (tid == 0) { mbar_init(mb0, 1); mbar_init(mb1, 1); }
    __syncthreads();
    if (tid == 0) {
        mbar_expect(mb0, ENC_SLICE_BYTES);
        bulk_cp(sWa, g_WtEnc, ENC_SLICE_BYTES, mb0);
        mbar_expect(mb1, ENC_SLICE_BYTES);
        bulk_cp(sWa + ENC_SLICE_BYTES, g_WtEnc + ENC_SLICE_FLOATS, ENC_SLICE_BYTES, mb1);
    }
    int ph0 = 0, ph1 = 0, sl = 0;
    const int NSL = 10 * 16;
    float bi0 = sbih[tl], bi1 = sbih[tl + 256], bi2 = sbih[tl + 512];
    float bh0 = sbhh[tl], bh1 = sbhh[tl + 256], bh2 = sbhh[tl + 512];

    for (int t = 0; t < 10; t++) {
        // fused accs for r,z gates; separate proj acc for n gate
        ull a0 = pk2(bi0 + bh0), a1 = pk2(bi1 + bh1), a2 = pk2(bh2), g2 = pk2(bi2);
        const float* sxc = sx + (t & 1) * 128;
        const float* w0p = sWih + tl * 33;
        const float* w1p = sWih + (tl + 256) * 33;
        const float* w2p = sWih + (tl + 512) * 33;
#pragma unroll
        for (int i = 0; i < 32; i++) {
            ull x2 = *reinterpret_cast<const ull*>(sxc + i * 4 + half * 2);
            FMA2(a0, pk2(w0p[i]), x2);
            FMA2(a1, pk2(w1p[i]), x2);
            FMA2(g2, pk2(w2p[i]), x2);
        }
        // prefetch next x into the other buffer
        if (t < 9 && tid < 128) {
            int b = tid >> 5, i = tid & 31;
            sx[((t + 1) & 1) * 128 + i * 4 + b] = X[((b0 + b) * TSEQ + (t + 1)) * NP + i];
        }

        for (int ks = 0; ks < 16; ks++) {
            int cur = sl & 1;
            if (cur == 0) { mbar_wait(mb0, ph0); ph0 ^= 1; }
            else          { mbar_wait(mb1, ph1); ph1 ^= 1; }
            const float* base = sW + cur * ENC_SLICE_FLOATS;
#pragma unroll
            for (int kl = 0; kl < 16; kl++) {
                const float* wr = base + kl * 768;
                ull w0 = pk2(wr[tl]), w1 = pk2(wr[tl + 256]), w2 = pk2(wr[tl + 512]);
                ull h2 = *reinterpret_cast<const ull*>(sh + (ks * 16 + kl) * 4 + half * 2);
                FMA2(a0, w0, h2); FMA2(a1, w1, h2); FMA2(a2, w2, h2);
            }
            __syncthreads();
            if (tid == 0 && sl + 2 < NSL) {
                uint32_t mb = cur ? mb1 : mb0;
                mbar_expect(mb, ENC_SLICE_BYTES);
                bulk_cp(sWa + cur * ENC_SLICE_BYTES,
                        g_WtEnc + (size_t)((sl + 2) & 15) * ENC_SLICE_FLOATS,
                        ENC_SLICE_BYTES, mb);
            }
            sl++;
        }
        float a0x, a0y, a1x, a1y, a2x, a2y, g2x, g2y;
        upk(a0, a0x, a0y); upk(a1, a1x, a1y); upk(a2, a2x, a2y); upk(g2, g2x, g2y);
        int bs = half * 2;
        {
            float r = sigm(a0x), z = sigm(a1x);
            float n = tanhf(g2x + r * a2x);
            sh[tl * 4 + bs] = (1.0f - z) * n + z * sh[tl * 4 + bs];
        }
        {
            float r = sigm(a0y), z = sigm(a1y);
            float n = tanhf(g2y + r * a2y);
            sh[tl * 4 + bs + 1] = (1.0f - z) * n + z * sh[tl * 4 + bs + 1];
        }
        __syncthreads();
    }
    g_henc[(b0 + half * 2 + 0) * NH + tl] = sh[tl * 4 + half * 2 + 0];
    g_henc[(b0 + half * 2 + 1) * NH + tl] = sh[tl * 4 + half * 2 + 1];
}

// ======================= latent: mu / log_var / z (coalesced via transposed fc weights) ==========
__global__ void __launch_bounds__(256)
lat_kernel(const float* __restrict__ eps, const float* __restrict__ mb,
           const float* __restrict__ sb_, float* __restrict__ out) {
    __shared__ float hh[NH];
    int b = blockIdx.x, tid = threadIdx.x;
    hh[tid] = g_henc[b * NH + tid];
    __syncthreads();
    float am = mb[tid], as = sb_[tid];
    const float* mT = g_mwT + tid;
    const float* sT = g_swT + tid;
#pragma unroll 8
    for (int k = 0; k < NH; k++) {
        float h = hh[k];
        am += mT[k * NH] * h;
        as += sT[k * NH] * h;
    }
    out[126976 + b * NH + tid] = am;   // mu
    out[110592 + b * NH + tid] = as;   // log_var
    g_z[b * NH + tid] = am + expf(0.5f * as) * eps[b * NH + tid];
}

// ======================= decoder input projection (batched GEMM, K=32) =======================
__global__ void __launch_bounds__(256, 1)
gi_kernel(const float* __restrict__ X, const float* __restrict__ Wih_all,
          const float* __restrict__ bih_all) {
    extern __shared__ float sm[];
    float* sWih = sm;          // 768*33 = 25344
    float* sxT  = sm + 25344;  // [i=32][66]
    int tid = threadIdx.x;
    int t = blockIdx.x, p = blockIdx.y;
    const float* Wih = Wih_all + p * NG * NP;
#pragma unroll
    for (int s = 0; s < 24; s++) {
        int fidx = tid + 256 * s;
        int j = fidx >> 3, iq = fidx & 7;
        float4 v = *reinterpret_cast<const float4*>(Wih + j * 32 + iq * 4);
        float* d = sWih + j * 33 + iq * 4;
        d[0] = v.x; d[1] = v.y; d[2] = v.z; d[3] = v.w;
    }
    for (int idx = tid; idx < 2048; idx += 256) {
        int b = idx >> 5, i = idx & 31;
        sxT[i * 66 + b] = (t == 0) ? 0.0f : X[(b * TSEQ + 9 + t) * NP + i];
    }
    float bi0 = bih_all[p * NG + tid];
    float bi1 = bih_all[p * NG + 256 + tid];
    float bi2 = bih_all[p * NG + 512 + tid];
    __syncthreads();
    float* og = g_gi + ((size_t)(p * TDEC + t) * NB) * NG;
    for (int bg = 0; bg < 4; bg++) {
        ull a0[8], a1[8], a2[8];
#pragma unroll
        for (int g = 0; g < 8; g++) { a0[g] = pk2(bi0); a1[g] = pk2(bi1); a2[g] = pk2(bi2); }
#pragma unroll
        for (int i = 0; i < 32; i++) {
            ull w0 = pk2(sWih[tid * 33 + i]);
            ull w1 = pk2(sWih[(tid + 256) * 33 + i]);
            ull w2 = pk2(sWih[(tid + 512) * 33 + i]);
            const ull* xp = reinterpret_cast<const ull*>(sxT + i * 66 + bg * 16);
#pragma unroll
            for (int g = 0; g < 8; g++) {
                ull x2 = xp[g];
                FMA2(a0[g], w0, x2); FMA2(a1[g], w1, x2); FMA2(a2[g], w2, x2);
            }
        }
#pragma unroll
        for (int g = 0; g < 8; g++) {
            float x0, x1;
            int b = bg * 16 + 2 * g;
            upk(a0[g], x0, x1); og[(size_t)b * NG + tid] = x0;       og[(size_t)(b + 1) * NG + tid] = x1;
            upk(a1[g], x0, x1); og[(size_t)b * NG + 256 + tid] = x0; og[(size_t)(b + 1) * NG + 256 + tid] = x1;
            upk(a2[g], x0, x1); og[(size_t)b * NG + 512 + tid] = x0; og[(size_t)(b + 1) * NG + 512 + tid] = x1;
        }
    }
}

// ======================= decoder GRU: 128 CTAs = 32 series x 4 batch-chunks, 512 thr =======================
// smem (floats): sW 0..49152 (2 x [32][768] slices), sh 49152..54272 ([k=256][20]),
//                sbhh 54272..55040, slw 55040..55296, mbar 55296..55300
#define DEC_SLICE_FLOATS (32 * 768)
#define DEC_SLICE_BYTES  (DEC_SLICE_FLOATS * 4)
__global__ void __launch_bounds__(512, 1)
dec_kernel(const float* __restrict__ bhh_all,
           const float* __restrict__ lw_all, const float* __restrict__ lb_all,
           float* __restrict__ out) {
    extern __shared__ float sm[];
    float* sW   = sm;
    float* sh   = sm + 49152;
    float* sbhh = sm + 54272;
    float* slw  = sm + 55040;
    float* smb  = sm + 55296;
    int tid = threadIdx.x;
    int half = tid >> 8;        // 0: batch rows 0-7, 1: rows 8-15
    int tl = tid & 255;         // gate-row index base
    int p = blockIdx.y, c = blockIdx.x, b0 = c * 16;
    const float* Wt = g_Wt + (size_t)p * NH * NG;
    uint32_t mb0 = smem_u32(smb), mb1 = mb0 + 8;
    uint32_t sWa = smem_u32(sW);
    for (int idx = tid; idx < 768; idx += 512) sbhh[idx] = bhh_all[p * NG + idx];
    if (tid < 256) slw[tid] = lw_all[p * NH + tid];
    float lb = lb_all[p];
    for (int idx = tid; idx < 4096; idx += 512) {
        int b = idx >> 8, k = idx & 255;
        sh[k * 20 + b] = g_z[(b0 + b) * NH + k];
    }
    if (tid == 0) { mbar_init(mb0, 1); mbar_init(mb1, 1); }
    __syncthreads();
    if (tid == 0) {
        mbar_expect(mb0, DEC_SLICE_BYTES);
        bulk_cp(sWa, Wt, DEC_SLICE_BYTES, mb0);
        mbar_expect(mb1, DEC_SLICE_BYTES);
        bulk_cp(sWa + DEC_SLICE_BYTES, Wt + DEC_SLICE_FLOATS, DEC_SLICE_BYTES, mb1);
    }
    int ph0 = 0, ph1 = 0, sl = 0;
    const int NSL = TDEC * 8;
    float bh0 = sbhh[tl], bh1 = sbhh[tl + 256], bh2 = sbhh[tl + 512];
    int w = tid >> 5, lane = tid & 31;

    for (int t = 0; t < TDEC; t++) {
        // ---- prefetch this step's gi (24 scalar, coalesced across tl) BEFORE the FMA loop ----
        const float* gip = g_gi + (((size_t)(p * TDEC + t) * NB) + b0 + half * 8) * NG + tl;
        float pg[24];
#pragma unroll
        for (int b = 0; b < 8; b++) {
            pg[b * 3 + 0] = gip[(size_t)b * NG];
            pg[b * 3 + 1] = gip[(size_t)b * NG + 256];
            pg[b * 3 + 2] = gip[(size_t)b * NG + 512];
        }

        ull a0[4], a1[4], a2[4];
#pragma unroll
        for (int g = 0; g < 4; g++) { a0[g] = pk2(bh0); a1[g] = pk2(bh1); a2[g] = pk2(bh2); }

        for (int ks = 0; ks < 8; ks++) {
            int cur = sl & 1;
            if (cur == 0) { mbar_wait(mb0, ph0); ph0 ^= 1; }
            else          { mbar_wait(mb1, ph1); ph1 ^= 1; }
            const float* base = sW + cur * DEC_SLICE_FLOATS;
#pragma unroll
            for (int kl = 0; kl < 32; kl++) {
                const float* wr = base + kl * 768;
                ull w0 = pk2(wr[tl]), w1 = pk2(wr[tl + 256]), w2 = pk2(wr[tl + 512]);
                const ulonglong2* hp = reinterpret_cast<const ulonglong2*>(
                    sh + (ks * 32 + kl) * 20 + half * 8);
                ulonglong2 hA = hp[0];
                ulonglong2 hB = hp[1];
                FMA2(a0[0], w0, hA.x); FMA2(a0[1], w0, hA.y);
                FMA2(a0[2], w0, hB.x); FMA2(a0[3], w0, hB.y);
                FMA2(a1[0], w1, hA.x); FMA2(a1[1], w1, hA.y);
                FMA2(a1[2], w1, hB.x); FMA2(a1[3], w1, hB.y);
                FMA2(a2[0], w2, hA.x); FMA2(a2[1], w2, hA.y);
                FMA2(a2[2], w2, hB.x); FMA2(a2[3], w2, hB.y);
            }
            __syncthreads();
            if (tid == 0 && sl + 2 < NSL) {
                uint32_t mb = cur ? mb1 : mb0;
                mbar_expect(mb, DEC_SLICE_BYTES);
                bulk_cp(sWa + cur * DEC_SLICE_BYTES,
                        Wt + (size_t)((sl + 2) & 7) * DEC_SLICE_FLOATS,
                        DEC_SLICE_BYTES, mb);
            }
            sl++;
        }
        // gates + h update: thread owns gate row tl for batch rows half*8 .. half*8+7
#pragma unroll
        for (int g = 0; g < 4; g++) {
            float a0x, a0y, a1x, a1y, a2x, a2y;
            upk(a0[g], a0x, a0y); upk(a1[g], a1x, a1y); upk(a2[g], a2x, a2y);
            int b = 2 * g;
            int bs = half * 8 + b;
            {
                float r = sigm(pg[b * 3 + 0] + a0x), z = sigm(pg[b * 3 + 1] + a1x);
                float n = tanhf(pg[b * 3 + 2] + r * a2x);
                sh[tl * 20 + bs] = (1.0f - z) * n + z * sh[tl * 20 + bs];
            }
            {
                float r = sigm(pg[(b + 1) * 3 + 0] + a0y), z = sigm(pg[(b + 1) * 3 + 1] + a1y);
                float n = tanhf(pg[(b + 1) * 3 + 2] + r * a2y);
                sh[tl * 20 + bs + 1] = (1.0f - z) * n + z * sh[tl * 20 + bs + 1];
            }
        }
        __syncthreads();
        // linear head: warp w reduces batch row w (16 warps, 16 rows)
        {
            float s = 0.0f;
#pragma unroll
            for (int m = 0; m < 8; m++) { int k = lane + 32 * m; s += slw[k] * sh[k * 20 + w]; }
#pragma unroll
            for (int off = 16; off; off >>= 1) s += __shfl_xor_sync(0xffffffffu, s, off);
            if (lane == 0) out[((size_t)p * NB + b0 + w) * TDEC + t] = s + lb;
        }
    }
}

// ======================= launcher =======================
extern "C" void kernel_launch(void* const* d_in, const int* in_sizes, int n_in,
                              void* d_out, int out_size) {
    const float* X       = (const float*)d_in[0];
    const float* eps     = (const float*)d_in[1];
    const float* Wih_enc = (const float*)d_in[2];
    const float* Whh_enc = (const float*)d_in[3];
    const float* bih_enc = (const float*)d_in[4];
    const float* bhh_enc = (const float*)d_in[5];
    const float* mw      = (const float*)d_in[6];
    const float* mb      = (const float*)d_in[7];
    const float* sw      = (const float*)d_in[8];
    const float* sb      = (const float*)d_in[9];
    const float* Wih_dec = (const float*)d_in[10];
    const float* Whh_dec = (const float*)d_in[11];
    const float* bih_dec = (const float*)d_in[12];
    const float* bhh_dec = (const float*)d_in[13];
    const float* lw      = (const float*)d_in[14];
    const float* lbv     = (const float*)d_in[15];
    float* out = (float*)d_out;

    int smem_enc = 52740 * 4;              // 210,960 B
    int smem_gi  = (25344 + 32 * 66) * 4;  // 109,824 B
    int smem_dec = 55300 * 4;              // 221,200 B
    cudaFuncSetAttribute(enc_kernel, cudaFuncAttributeMaxDynamicSharedMemorySize, smem_enc);
    cudaFuncSetAttribute(gi_kernel,  cudaFuncAttributeMaxDynamicSharedMemorySize, smem_gi);
    cudaFuncSetAttribute(dec_kernel, cudaFuncAttributeMaxDynamicSharedMemorySize, smem_dec);

    tr_kernel<<<dim3(8, 24, 32), dim3(32, 8)>>>(Whh_dec);
    tr_enc_kernel<<<dim3(8, 24), dim3(32, 8)>>>(Whh_enc);
    trf_kernel<<<dim3(8, 8, 2), dim3(32, 8)>>>(mw, sw);
    gi_kernel<<<dim3(TDEC, NP), 256, smem_gi>>>(X, Wih_dec, bih_dec);
    enc_kernel<<<16, 512, smem_enc>>>(X, Wih_enc, bih_enc, bhh_enc);
    lat_kernel<<<NB, 256>>>(eps, mb, sb, out);
    dec_kernel<<<dim3(4, NP), 512, smem_dec>>>(bhh_dec, lw, lbv, out);
}

// round 15
// speedup vs baseline: 3.3937x; 1.8141x over previous
#include <cuda_runtime.h>
#include <cuda_fp16.h>
#include <math.h>
#include <stdint.h>

typedef unsigned long long ull;

#define NB 64
#define NH 256
#define NG 768
#define NP 32
#define TSEQ 64
#define TDEC 54

// -------- device-global scratch --------
__device__ float g_gi[84934656];        // [p][t][j=768][b=64] input-proj (incl b_ih)
__device__ float g_z[NB * NH];
__device__ float g_henc[NB * NH];
__device__ float g_WtEnc[256 * 768];    // W_hh_enc^T [k][j]
__device__ float g_mwT[NH * NH];
__device__ float g_swT[NH * NH];
__device__ __half g_Wfrag[32 * 196608]; // [p][slice 8][frag-order 24576 halfs] fp16 W_hh_dec

// -------- f32x2 helpers --------
__device__ __forceinline__ ull pk(float x, float y) {
    ull r; asm("mov.b64 %0, {%1,%2};" : "=l"(r) : "f"(x), "f"(y)); return r;
}
__device__ __forceinline__ ull pk2(float x) { return pk(x, x); }
__device__ __forceinline__ void upk(ull v, float& x, float& y) {
    asm("mov.b64 {%0,%1}, %2;" : "=f"(x), "=f"(y) : "l"(v));
}
#define FMA2(acc, a, b) asm("fma.rn.f32x2 %0, %1, %2, %0;" : "+l"(acc) : "l"(a), "l"(b))
__device__ __forceinline__ float sigm(float x) { return 1.0f / (1.0f + expf(-x)); }

// -------- mbarrier / bulk-copy helpers --------
__device__ __forceinline__ uint32_t smem_u32(const void* p) {
    uint32_t a;
    asm("{ .reg .u64 t; cvta.to.shared.u64 t, %1; cvt.u32.u64 %0, t; }" : "=r"(a) : "l"(p));
    return a;
}
__device__ __forceinline__ void mbar_init(uint32_t m, uint32_t c) {
    asm volatile("mbarrier.init.shared.b64 [%0], %1;" :: "r"(m), "r"(c) : "memory");
}
__device__ __forceinline__ void mbar_expect(uint32_t m, uint32_t b) {
    asm volatile("mbarrier.arrive.expect_tx.shared.b64 _, [%0], %1;" :: "r"(m), "r"(b) : "memory");
}
__device__ __forceinline__ void bulk_cp(uint32_t dst, const void* src, uint32_t bytes, uint32_t m) {
    asm volatile("cp.async.bulk.shared::cluster.global.mbarrier::complete_tx::bytes [%0], [%1], %2, [%3];"
        :: "r"(dst), "l"(src), "r"(bytes), "r"(m) : "memory");
}
__device__ __forceinline__ void mbar_wait(uint32_t m, uint32_t ph) {
    asm volatile(
        "{\n\t.reg .pred P1;\n\tW%=:\n\t"
        "mbarrier.try_wait.parity.acquire.cta.shared::cta.b64 P1, [%0], %1, 0x989680;\n\t"
        "@P1 bra.uni D%=;\n\tbra.uni W%=;\n\tD%=:\n\t}" :: "r"(m), "r"(ph) : "memory");
}

// -------- HMMA m16n8k16 fp16 -> fp32 --------
__device__ __forceinline__ void hmma(float* c, const uint4& a, uint32_t b0, uint32_t b1) {
    asm("mma.sync.aligned.m16n8k16.row.col.f32.f16.f16.f32 "
        "{%0,%1,%2,%3}, {%4,%5,%6,%7}, {%8,%9}, {%0,%1,%2,%3};"
        : "+f"(c[0]), "+f"(c[1]), "+f"(c[2]), "+f"(c[3])
        : "r"(a.x), "r"(a.y), "r"(a.z), "r"(a.w), "r"(b0), "r"(b1));
}
__device__ __forceinline__ uint32_t h2pack(float a, float b) {
    __half2 v = __floats2half2_rn(a, b);
    return *reinterpret_cast<uint32_t*>(&v);
}

// ======================= W_hh_dec -> fp16 fragment-order pack =======================
// frag (mt 0..47, kt 0..15, lane): A rows mt*16 + {lane>>2, +8}, cols kt*16 + {(lane&3)*2,+1, +8,+9}
__global__ void wprep_kernel(const float* __restrict__ W) {
    int p = blockIdx.y;
    int i = blockIdx.x * 256 + threadIdx.x;   // 0..24575
    int mt = i >> 9, kt = (i >> 5) & 15, lane = i & 31;
    int row = mt * 16 + (lane >> 2);
    int k0 = kt * 16 + ((lane & 3) << 1);
    const float* Wp = W + (size_t)p * NG * NH;
    float2 v0 = *reinterpret_cast<const float2*>(Wp + (size_t)row * NH + k0);
    float2 v1 = *reinterpret_cast<const float2*>(Wp + (size_t)(row + 8) * NH + k0);
    float2 v2 = *reinterpret_cast<const float2*>(Wp + (size_t)row * NH + k0 + 8);
    float2 v3 = *reinterpret_cast<const float2*>(Wp + (size_t)(row + 8) * NH + k0 + 8);
    uint4 o = make_uint4(h2pack(v0.x, v0.y), h2pack(v1.x, v1.y),
                         h2pack(v2.x, v2.y), h2pack(v3.x, v3.y));
    size_t dst = (size_t)p * 196608 + (size_t)(kt >> 1) * 24576
               + (size_t)((mt * 2 + (kt & 1)) * 32 + lane) * 8;
    *reinterpret_cast<uint4*>(g_Wfrag + dst) = o;
}

// ======================= W_hh_enc transpose =======================
__global__ void tr_enc_kernel(const float* __restrict__ W) {
    __shared__ float tile[32][33];
    int k0 = blockIdx.x * 32, j0 = blockIdx.y * 32;
    int x = threadIdx.x, y0 = threadIdx.y;
#pragma unroll
    for (int dy = 0; dy < 32; dy += 8) tile[y0 + dy][x] = W[(j0 + y0 + dy) * NH + k0 + x];
    __syncthreads();
#pragma unroll
    for (int dy = 0; dy < 32; dy += 8) g_WtEnc[(k0 + y0 + dy) * NG + j0 + x] = tile[x][y0 + dy];
}

// ======================= fc weight transpose (x2) =======================
__global__ void trf_kernel(const float* __restrict__ mw, const float* __restrict__ sw_) {
    __shared__ float tile[32][33];
    int sel = blockIdx.z;
    const float* Wp = sel ? sw_ : mw;
    float* Wtp = sel ? g_swT : g_mwT;
    int k0 = blockIdx.x * 32, j0 = blockIdx.y * 32;
    int x = threadIdx.x, y0 = threadIdx.y;
#pragma unroll
    for (int dy = 0; dy < 32; dy += 8) tile[y0 + dy][x] = Wp[(j0 + y0 + dy) * NH + k0 + x];
    __syncthreads();
#pragma unroll
    for (int dy = 0; dy < 32; dy += 8) Wtp[(k0 + y0 + dy) * NH + j0 + x] = tile[x][y0 + dy];
}

// ======================= encoder GRU (TMA-streamed fp32) =======================
#define ENC_SF (16 * 768)
#define ENC_SB (ENC_SF * 4)
__global__ void __launch_bounds__(512, 1)
enc_kernel(const float* __restrict__ X, const float* __restrict__ Wih,
           const float* __restrict__ bih, const float* __restrict__ bhh) {
    extern __shared__ __align__(1024) float sm[];
    float* sW = sm;           float* sWih = sm + 24576;
    float* sh = sm + 49920;   float* sbih = sm + 50944;
    float* sbhh = sm + 51712; float* sx = sm + 52480;
    float* smb = sm + 52736;
    int tid = threadIdx.x, half = tid >> 8, tl = tid & 255;
    int b0 = blockIdx.x * 4;
    uint32_t mb0 = smem_u32(smb), mb1 = mb0 + 8, sWa = smem_u32(sW);
#pragma unroll
    for (int s = 0; s < 12; s++) {
        int fidx = tid + 512 * s;
        int j = fidx >> 3, iq = fidx & 7;
        float4 v = *reinterpret_cast<const float4*>(Wih + j * 32 + iq * 4);
        float* d = sWih + j * 33 + iq * 4;
        d[0] = v.x; d[1] = v.y; d[2] = v.z; d[3] = v.w;
    }
    for (int i = tid; i < 768; i += 512) { sbih[i] = bih[i]; sbhh[i] = bhh[i]; }
    for (int i = tid; i < 1024; i += 512) sh[i] = 0.0f;
    if (tid < 128) { int b = tid >> 5, i = tid & 31; sx[i * 4 + b] = X[((b0 + b) * TSEQ) * NP + i]; }
    if (tid == 0) { mbar_init(mb0, 1); mbar_init(mb1, 1); }
    __syncthreads();
    if (tid == 0) {
        mbar_expect(mb0, ENC_SB); bulk_cp(sWa, g_WtEnc, ENC_SB, mb0);
        mbar_expect(mb1, ENC_SB); bulk_cp(sWa + ENC_SB, g_WtEnc + ENC_SF, ENC_SB, mb1);
    }
    int ph0 = 0, ph1 = 0, sl = 0;
    const int NSL = 160;
    float bi0 = sbih[tl], bi1 = sbih[tl + 256], bi2 = sbih[tl + 512];
    float bh0 = sbhh[tl], bh1 = sbhh[tl + 256], bh2 = sbhh[tl + 512];
    for (int t = 0; t < 10; t++) {
        ull a0 = pk2(bi0 + bh0), a1 = pk2(bi1 + bh1), a2 = pk2(bh2), g2 = pk2(bi2);
        const float* sxc = sx + (t & 1) * 128;
        const float* w0p = sWih + tl * 33;
        const float* w1p = sWih + (tl + 256) * 33;
        const float* w2p = sWih + (tl + 512) * 33;
#pragma unroll
        for (int i = 0; i < 32; i++) {
            ull x2 = *reinterpret_cast<const ull*>(sxc + i * 4 + half * 2);
            FMA2(a0, pk2(w0p[i]), x2); FMA2(a1, pk2(w1p[i]), x2); FMA2(g2, pk2(w2p[i]), x2);
        }
        if (t < 9 && tid < 128) {
            int b = tid >> 5, i = tid & 31;
            sx[((t + 1) & 1) * 128 + i * 4 + b] = X[((b0 + b) * TSEQ + t + 1) * NP + i];
        }
        for (int ks = 0; ks < 16; ks++) {
            int cur = sl & 1;
            if (cur == 0) { mbar_wait(mb0, ph0); ph0 ^= 1; } else { mbar_wait(mb1, ph1); ph1 ^= 1; }
            const float* base = sW + cur * ENC_SF;
#pragma unroll
            for (int kl = 0; kl < 16; kl++) {
                const float* wr = base + kl * 768;
                ull w0 = pk2(wr[tl]), w1 = pk2(wr[tl + 256]), w2 = pk2(wr[tl + 512]);
                ull h2 = *reinterpret_cast<const ull*>(sh + (ks * 16 + kl) * 4 + half * 2);
                FMA2(a0, w0, h2); FMA2(a1, w1, h2); FMA2(a2, w2, h2);
            }
            __syncthreads();
            if (tid == 0 && sl + 2 < NSL) {
                uint32_t mb = cur ? mb1 : mb0;
                mbar_expect(mb, ENC_SB);
                bulk_cp(sWa + cur * ENC_SB, g_WtEnc + (size_t)((sl + 2) & 15) * ENC_SF, ENC_SB, mb);
            }
            sl++;
        }
        float a0x, a0y, a1x, a1y, a2x, a2y, g2x, g2y;
        upk(a0, a0x, a0y); upk(a1, a1x, a1y); upk(a2, a2x, a2y); upk(g2, g2x, g2y);
        int bs = half * 2;
        { float r = sigm(a0x), z = sigm(a1x); float n = tanhf(g2x + r * a2x);
          sh[tl * 4 + bs] = (1.0f - z) * n + z * sh[tl * 4 + bs]; }
        { float r = sigm(a0y), z = sigm(a1y); float n = tanhf(g2y + r * a2y);
          sh[tl * 4 + bs + 1] = (1.0f - z) * n + z * sh[tl * 4 + bs + 1]; }
        __syncthreads();
    }
    g_henc[(b0 + half * 2 + 0) * NH + tl] = sh[tl * 4 + half * 2 + 0];
    g_henc[(b0 + half * 2 + 1) * NH + tl] = sh[tl * 4 + half * 2 + 1];
}

// ======================= latent =======================
__global__ void __launch_bounds__(256)
lat_kernel(const float* __restrict__ eps, const float* __restrict__ mb,
           const float* __restrict__ sb_, float* __restrict__ out) {
    __shared__ float hh[NH];
    int b = blockIdx.x, tid = threadIdx.x;
    hh[tid] = g_henc[b * NH + tid];
    __syncthreads();
    float am = mb[tid], as = sb_[tid];
    const float* mT = g_mwT + tid;
    const float* sT = g_swT + tid;
#pragma unroll 8
    for (int k = 0; k < NH; k++) { float h = hh[k]; am += mT[k * NH] * h; as += sT[k * NH] * h; }
    out[126976 + b * NH + tid] = am;
    out[110592 + b * NH + tid] = as;
    g_z[b * NH + tid] = am + expf(0.5f * as) * eps[b * NH + tid];
}

// ======================= decoder input projection -> g_gi [p][t][j][b] =======================
__global__ void __launch_bounds__(256, 1)
gi_kernel(const float* __restrict__ X, const float* __restrict__ Wih_all,
          const float* __restrict__ bih_all) {
    extern __shared__ float sm[];
    float* sWih = sm;          // 768*33
    float* sxT = sm + 25344;   // [i=32][66]
    int tid = threadIdx.x, t = blockIdx.x, p = blockIdx.y;
    const float* Wih = Wih_all + p * NG * NP;
#pragma unroll
    for (int s = 0; s < 24; s++) {
        int fidx = tid + 256 * s;
        int j = fidx >> 3, iq = fidx & 7;
        float4 v = *reinterpret_cast<const float4*>(Wih + j * 32 + iq * 4);
        float* d = sWih + j * 33 + iq * 4;
        d[0] = v.x; d[1] = v.y; d[2] = v.z; d[3] = v.w;
    }
    for (int i = tid; i < 2048; i += 256) {
        int b = i >> 5, ii = i & 31;
        sxT[ii * 66 + b] = (t == 0) ? 0.0f : X[(b * TSEQ + 9 + t) * NP + ii];
    }
    float bi0 = bih_all[p * NG + tid];
    float bi1 = bih_all[p * NG + 256 + tid];
    float bi2 = bih_all[p * NG + 512 + tid];
    __syncthreads();
    float* og = g_gi + (size_t)(p * TDEC + t) * NG * NB;
    for (int bg = 0; bg < 4; bg++) {
        ull a0[8], a1[8], a2[8];
#pragma unroll
        for (int g = 0; g < 8; g++) { a0[g] = pk2(bi0); a1[g] = pk2(bi1); a2[g] = pk2(bi2); }
#pragma unroll
        for (int i = 0; i < 32; i++) {
            ull w0 = pk2(sWih[tid * 33 + i]);
            ull w1 = pk2(sWih[(tid + 256) * 33 + i]);
            ull w2 = pk2(sWih[(tid + 512) * 33 + i]);
            const ull* xp = reinterpret_cast<const ull*>(sxT + i * 66 + bg * 16);
#pragma unroll
            for (int g = 0; g < 8; g++) {
                ull x2 = xp[g];
                FMA2(a0[g], w0, x2); FMA2(a1[g], w1, x2); FMA2(a2[g], w2, x2);
            }
        }
        float v[3][16];
#pragma unroll
        for (int g = 0; g < 8; g++) {
            upk(a0[g], v[0][2 * g], v[0][2 * g + 1]);
            upk(a1[g], v[1][2 * g], v[1][2 * g + 1]);
            upk(a2[g], v[2][2 * g], v[2][2 * g + 1]);
        }
#pragma unroll
        for (int gate = 0; gate < 3; gate++) {
            float* d = og + (size_t)(gate * 256 + tid) * NB + bg * 16;
#pragma unroll
            for (int q = 0; q < 4; q++)
                *reinterpret_cast<float4*>(d + 4 * q) =
                    make_float4(v[gate][4 * q], v[gate][4 * q + 1], v[gate][4 * q + 2], v[gate][4 * q + 3]);
        }
    }
}

// ======================= decoder GRU via mma.sync fp16, 128 CTAs x 512 thr =======================
// SMEM: 2x48KB W slots | shi [16][264] f16 | slo [16][264] f16 | bhh 768f | lw 256f | sout 32f | mbars
#define SLOT_B   49152
#define OFF_SHI  98304
#define OFF_SLO  106752
#define OFF_BHH  115200
#define OFF_LW   118272
#define OFF_SOUT 119296
#define OFF_MB   119424
#define DEC_SMEM 119552

__global__ void __launch_bounds__(512, 1)
dec_mma_kernel(const float* __restrict__ bhh_all, const float* __restrict__ lw_all,
               const float* __restrict__ lb_all, float* __restrict__ out) {
    extern __shared__ __align__(128) char smc[];
    __half* shi = (__half*)(smc + OFF_SHI);
    __half* slo = (__half*)(smc + OFF_SLO);
    float* sbhh = (float*)(smc + OFF_BHH);
    float* slw  = (float*)(smc + OFF_LW);
    float* sout = (float*)(smc + OFF_SOUT);
    int tid = threadIdx.x, lane = tid & 31, w = tid >> 5;
    int p = blockIdx.y, c = blockIdx.x, b0 = c * 16;
    uint32_t sb = smem_u32(smc);
    uint32_t wmb[2] = { sb + OFF_MB, sb + OFF_MB + 8 };

    for (int i = tid; i < 768; i += 512) sbhh[i] = bhh_all[p * NG + i];
    if (tid < 256) slw[tid] = lw_all[p * NH + tid];
    if (tid < 32) sout[tid] = 0.0f;
    float lb = lb_all[p];
    // h images from z (fp16 hi/lo split)
    for (int i = tid; i < 4096; i += 512) {
        int b = i >> 8, j = i & 255;
        float z = g_z[(b0 + b) * NH + j];
        __half hi = __float2half(z);
        shi[b * 264 + j] = hi;
        slo[b * 264 + j] = __float2half(z - __half2float(hi));
    }
    if (tid == 0) { mbar_init(wmb[0], 1); mbar_init(wmb[1], 1); }
    __syncthreads();
    const __half* Wf = g_Wfrag + (size_t)p * 196608;
    if (tid == 0) {
        mbar_expect(wmb[0], SLOT_B); bulk_cp(sb, Wf, SLOT_B, wmb[0]);
        mbar_expect(wmb[1], SLOT_B); bulk_cp(sb + SLOT_B, Wf + 24576, SLOT_B, wmb[1]);
    }
    int wph[2] = {0, 0};
    int gsl = 0;
    const int NSLT = TDEC * 8;
    int tr0 = lane >> 2, cb0 = (lane & 3) << 1;

    for (int t = 0; t < TDEC; t++) {
        // ---- prefetch gi: [jj][g][nt] float2 over (cs) ----
        const float* gib = g_gi + (size_t)(p * TDEC + t) * NG * NB;
        float2 pg[2][3][2];
#pragma unroll
        for (int jj = 0; jj < 2; jj++) {
            int jrow = w * 16 + tr0 + jj * 8;
#pragma unroll
            for (int g = 0; g < 3; g++) {
                const float* rb = gib + (size_t)(g * 256 + jrow) * NB + b0 + cb0;
                pg[jj][g][0] = *reinterpret_cast<const float2*>(rb);
                pg[jj][g][1] = *reinterpret_cast<const float2*>(rb + 8);
            }
        }
        float acc[3][2][4];
#pragma unroll
        for (int g = 0; g < 3; g++)
#pragma unroll
            for (int nt = 0; nt < 2; nt++)
#pragma unroll
                for (int q = 0; q < 4; q++) acc[g][nt][q] = 0.0f;

        // ---- MMA over 8 k-slices (2 passes: W*hhi + W*hlo) ----
        for (int s8 = 0; s8 < 8; s8++) {
            int slot = gsl & 1;
            mbar_wait(wmb[slot], wph[slot]); wph[slot] ^= 1;
            const __half* slab = (const __half*)(smc + slot * SLOT_B);
#pragma unroll
            for (int ktl = 0; ktl < 2; ktl++) {
                int k0 = s8 * 32 + ktl * 16 + cb0;
                uint32_t bh[2][2], bl[2][2];
#pragma unroll
                for (int nt = 0; nt < 2; nt++) {
                    int n = nt * 8 + tr0;
                    bh[nt][0] = *reinterpret_cast<const uint32_t*>(shi + n * 264 + k0);
                    bh[nt][1] = *reinterpret_cast<const uint32_t*>(shi + n * 264 + k0 + 8);
                    bl[nt][0] = *reinterpret_cast<const uint32_t*>(slo + n * 264 + k0);
                    bl[nt][1] = *reinterpret_cast<const uint32_t*>(slo + n * 264 + k0 + 8);
                }
#pragma unroll
                for (int g = 0; g < 3; g++) {
                    int mt = g * 16 + w;
                    uint4 a = *reinterpret_cast<const uint4*>(slab + ((mt * 2 + ktl) * 32 + lane) * 8);
                    hmma(acc[g][0], a, bh[0][0], bh[0][1]);
                    hmma(acc[g][1], a, bh[1][0], bh[1][1]);
                    hmma(acc[g][0], a, bl[0][0], bl[0][1]);
                    hmma(acc[g][1], a, bl[1][0], bl[1][1]);
                }
            }
            __syncthreads();
            if (tid == 0 && gsl + 2 < NSLT) {
                mbar_expect(wmb[slot], SLOT_B);
                bulk_cp(sb + slot * SLOT_B, Wf + (size_t)((gsl + 2) & 7) * 24576, SLOT_B, wmb[slot]);
            }
            gsl++;
        }

        // ---- epilogue: gates, h update, linear head ----
        float red[2][2] = {{0.0f, 0.0f}, {0.0f, 0.0f}};
#pragma unroll
        for (int jj = 0; jj < 2; jj++) {
            int j = w * 16 + tr0 + jj * 8;
            float br = sbhh[j], bz = sbhh[256 + j], bn = sbhh[512 + j];
            float lwj = slw[j];
#pragma unroll
            for (int nt = 0; nt < 2; nt++) {
#pragma unroll
                for (int cs = 0; cs < 2; cs++) {
                    int ci = jj * 2 + cs;
                    int b = nt * 8 + cb0 + cs;
                    float hold = __half2float(shi[b * 264 + j]) + __half2float(slo[b * 264 + j]);
                    float gr = (cs == 0) ? pg[jj][0][nt].x : pg[jj][0][nt].y;
                    float gz = (cs == 0) ? pg[jj][1][nt].x : pg[jj][1][nt].y;
                    float gn = (cs == 0) ? pg[jj][2][nt].x : pg[jj][2][nt].y;
                    float r = sigm(gr + br + acc[0][nt][ci]);
                    float z = sigm(gz + bz + acc[1][nt][ci]);
                    float n = tanhf(gn + r * (bn + acc[2][nt][ci]));
                    float hv = (1.0f - z) * n + z * hold;
                    __half hh = __float2half(hv);
                    shi[b * 264 + j] = hh;
                    slo[b * 264 + j] = __float2half(hv - __half2float(hh));
                    red[nt][cs] += lwj * hv;
                }
            }
        }
#pragma unroll
        for (int nt = 0; nt < 2; nt++)
#pragma unroll
            for (int cs = 0; cs < 2; cs++) {
                float v = red[nt][cs];
                v += __shfl_xor_sync(0xffffffffu, v, 4);
                v += __shfl_xor_sync(0xffffffffu, v, 8);
                v += __shfl_xor_sync(0xffffffffu, v, 16);
                if (tr0 == 0) atomicAdd(sout + (t & 1) * 16 + nt * 8 + cb0 + cs, v);
            }
        __syncthreads();
        if (tid < 16) {
            out[((size_t)p * NB + b0 + tid) * TDEC + t] = sout[(t & 1) * 16 + tid] + lb;
            sout[(t & 1) * 16 + tid] = 0.0f;   // reused at t+2; ordered by t+1's barriers
        }
    }
}

// ======================= launcher =======================
extern "C" void kernel_launch(void* const* d_in, const int* in_sizes, int n_in,
                              void* d_out, int out_size) {
    const float* X       = (const float*)d_in[0];
    const float* eps     = (const float*)d_in[1];
    const float* Wih_enc = (const float*)d_in[2];
    const float* Whh_enc = (const float*)d_in[3];
    const float* bih_enc = (const float*)d_in[4];
    const float* bhh_enc = (const float*)d_in[5];
    const float* mw      = (const float*)d_in[6];
    const float* mb      = (const float*)d_in[7];
    const float* sw      = (const float*)d_in[8];
    const float* sb      = (const float*)d_in[9];
    const float* Wih_dec = (const float*)d_in[10];
    const float* Whh_dec = (const float*)d_in[11];
    const float* bih_dec = (const float*)d_in[12];
    const float* bhh_dec = (const float*)d_in[13];
    const float* lw      = (const float*)d_in[14];
    const float* lbv     = (const float*)d_in[15];
    float* out = (float*)d_out;

    int smem_enc = 52740 * 4;
    int smem_gi  = (25344 + 32 * 66) * 4;
    cudaFuncSetAttribute(enc_kernel,     cudaFuncAttributeMaxDynamicSharedMemorySize, smem_enc);
    cudaFuncSetAttribute(gi_kernel,      cudaFuncAttributeMaxDynamicSharedMemorySize, smem_gi);
    cudaFuncSetAttribute(dec_mma_kernel, cudaFuncAttributeMaxDynamicSharedMemorySize, DEC_SMEM);

    wprep_kernel<<<dim3(96, 32), 256>>>(Whh_dec);
    tr_enc_kernel<<<dim3(8, 24), dim3(32, 8)>>>(Whh_enc);
    trf_kernel<<<dim3(8, 8, 2), dim3(32, 8)>>>(mw, sw);
    gi_kernel<<<dim3(TDEC, NP), 256, smem_gi>>>(X, Wih_dec, bih_dec);
    enc_kernel<<<16, 512, smem_enc>>>(X, Wih_enc, bih_enc, bhh_enc);
    lat_kernel<<<NB, 256>>>(eps, mb, sb, out);
    dec_mma_kernel<<<dim3(4, NP), 512, DEC_SMEM>>>(bhh_dec, lw, lbv, out);
}

// round 16
// speedup vs baseline: 4.4482x; 1.3107x over previous
#include <cuda_runtime.h>
#include <cuda_fp16.h>
#include <math.h>
#include <stdint.h>

typedef unsigned long long ull;

#define NB 64
#define NH 256
#define NG 768
#define NP 32
#define TSEQ 64
#define TDEC 54

// -------- device-global scratch --------
__device__ float g_z[NB * NH];
__device__ float g_henc[NB * NH];
__device__ float g_WtEnc[256 * 768];      // W_hh_enc^T [k][j]
__device__ float g_mwT[NH * NH];
__device__ float g_swT[NH * NH];
__device__ __half g_Wfrag[32 * 196608];   // [p][slice 8][24576 halfs] fp16 W_hh_dec frag-order
__device__ __half g_WihFrag[32 * 24576];  // [p][24576 halfs] fp16 W_ih_dec frag-order (K=32)

// -------- f32x2 helpers --------
__device__ __forceinline__ ull pk(float x, float y) {
    ull r; asm("mov.b64 %0, {%1,%2};" : "=l"(r) : "f"(x), "f"(y)); return r;
}
__device__ __forceinline__ ull pk2(float x) { return pk(x, x); }
__device__ __forceinline__ void upk(ull v, float& x, float& y) {
    asm("mov.b64 {%0,%1}, %2;" : "=f"(x), "=f"(y) : "l"(v));
}
#define FMA2(acc, a, b) asm("fma.rn.f32x2 %0, %1, %2, %0;" : "+l"(acc) : "l"(a), "l"(b))
__device__ __forceinline__ float sigm(float x) { return 1.0f / (1.0f + expf(-x)); }

// -------- mbarrier / bulk-copy helpers --------
__device__ __forceinline__ uint32_t smem_u32(const void* p) {
    uint32_t a;
    asm("{ .reg .u64 t; cvta.to.shared.u64 t, %1; cvt.u32.u64 %0, t; }" : "=r"(a) : "l"(p));
    return a;
}
__device__ __forceinline__ void mbar_init(uint32_t m, uint32_t c) {
    asm volatile("mbarrier.init.shared.b64 [%0], %1;" :: "r"(m), "r"(c) : "memory");
}
__device__ __forceinline__ void mbar_expect(uint32_t m, uint32_t b) {
    asm volatile("mbarrier.arrive.expect_tx.shared.b64 _, [%0], %1;" :: "r"(m), "r"(b) : "memory");
}
__device__ __forceinline__ void bulk_cp(uint32_t dst, const void* src, uint32_t bytes, uint32_t m) {
    asm volatile("cp.async.bulk.shared::cluster.global.mbarrier::complete_tx::bytes [%0], [%1], %2, [%3];"
        :: "r"(dst), "l"(src), "r"(bytes), "r"(m) : "memory");
}
__device__ __forceinline__ void mbar_wait(uint32_t m, uint32_t ph) {
    asm volatile(
        "{\n\t.reg .pred P1;\n\tW%=:\n\t"
        "mbarrier.try_wait.parity.acquire.cta.shared::cta.b64 P1, [%0], %1, 0x989680;\n\t"
        "@P1 bra.uni D%=;\n\tbra.uni W%=;\n\tD%=:\n\t}" :: "r"(m), "r"(ph) : "memory");
}

// -------- HMMA m16n8k16 fp16 -> fp32 --------
__device__ __forceinline__ void hmma(float* c, const uint4& a, uint32_t b0, uint32_t b1) {
    asm("mma.sync.aligned.m16n8k16.row.col.f32.f16.f16.f32 "
        "{%0,%1,%2,%3}, {%4,%5,%6,%7}, {%8,%9}, {%0,%1,%2,%3};"
        : "+f"(c[0]), "+f"(c[1]), "+f"(c[2]), "+f"(c[3])
        : "r"(a.x), "r"(a.y), "r"(a.z), "r"(a.w), "r"(b0), "r"(b1));
}
__device__ __forceinline__ uint32_t h2pack(float a, float b) {
    __half2 v = __floats2half2_rn(a, b);
    return *reinterpret_cast<uint32_t*>(&v);
}

// ======================= W_hh_dec -> fp16 fragment-order pack =======================
__global__ void wprep_kernel(const float* __restrict__ W) {
    int p = blockIdx.y;
    int i = blockIdx.x * 256 + threadIdx.x;   // 0..24575
    int mt = i >> 9, kt = (i >> 5) & 15, lane = i & 31;
    int row = mt * 16 + (lane >> 2);
    int k0 = kt * 16 + ((lane & 3) << 1);
    const float* Wp = W + (size_t)p * NG * NH;
    float2 v0 = *reinterpret_cast<const float2*>(Wp + (size_t)row * NH + k0);
    float2 v1 = *reinterpret_cast<const float2*>(Wp + (size_t)(row + 8) * NH + k0);
    float2 v2 = *reinterpret_cast<const float2*>(Wp + (size_t)row * NH + k0 + 8);
    float2 v3 = *reinterpret_cast<const float2*>(Wp + (size_t)(row + 8) * NH + k0 + 8);
    uint4 o = make_uint4(h2pack(v0.x, v0.y), h2pack(v1.x, v1.y),
                         h2pack(v2.x, v2.y), h2pack(v3.x, v3.y));
    size_t dst = (size_t)p * 196608 + (size_t)(kt >> 1) * 24576
               + (size_t)((mt * 2 + (kt & 1)) * 32 + lane) * 8;
    *reinterpret_cast<uint4*>(g_Wfrag + dst) = o;
}

// ======================= W_ih_dec -> fp16 fragment-order pack (K=32, 2 k-tiles) ==============
__global__ void wprep_ih_kernel(const float* __restrict__ W) {
    int p = blockIdx.y;
    int i = blockIdx.x * 256 + threadIdx.x;   // 0..3071 = 48 mt x 2 kt x 32 lane
    int mt = i >> 6, kt = (i >> 5) & 1, lane = i & 31;
    int row = mt * 16 + (lane >> 2);
    int k0 = kt * 16 + ((lane & 3) << 1);
    const float* Wp = W + (size_t)p * NG * NP;
    float2 v0 = *reinterpret_cast<const float2*>(Wp + (size_t)row * NP + k0);
    float2 v1 = *reinterpret_cast<const float2*>(Wp + (size_t)(row + 8) * NP + k0);
    float2 v2 = *reinterpret_cast<const float2*>(Wp + (size_t)row * NP + k0 + 8);
    float2 v3 = *reinterpret_cast<const float2*>(Wp + (size_t)(row + 8) * NP + k0 + 8);
    uint4 o = make_uint4(h2pack(v0.x, v0.y), h2pack(v1.x, v1.y),
                         h2pack(v2.x, v2.y), h2pack(v3.x, v3.y));
    size_t dst = (size_t)p * 24576 + (size_t)((mt * 2 + kt) * 32 + lane) * 8;
    *reinterpret_cast<uint4*>(g_WihFrag + dst) = o;
}

// ======================= W_hh_enc transpose =======================
__global__ void tr_enc_kernel(const float* __restrict__ W) {
    __shared__ float tile[32][33];
    int k0 = blockIdx.x * 32, j0 = blockIdx.y * 32;
    int x = threadIdx.x, y0 = threadIdx.y;
#pragma unroll
    for (int dy = 0; dy < 32; dy += 8) tile[y0 + dy][x] = W[(j0 + y0 + dy) * NH + k0 + x];
    __syncthreads();
#pragma unroll
    for (int dy = 0; dy < 32; dy += 8) g_WtEnc[(k0 + y0 + dy) * NG + j0 + x] = tile[x][y0 + dy];
}

// ======================= fc weight transpose (x2) =======================
__global__ void trf_kernel(const float* __restrict__ mw, const float* __restrict__ sw_) {
    __shared__ float tile[32][33];
    int sel = blockIdx.z;
    const float* Wp = sel ? sw_ : mw;
    float* Wtp = sel ? g_swT : g_mwT;
    int k0 = blockIdx.x * 32, j0 = blockIdx.y * 32;
    int x = threadIdx.x, y0 = threadIdx.y;
#pragma unroll
    for (int dy = 0; dy < 32; dy += 8) tile[y0 + dy][x] = Wp[(j0 + y0 + dy) * NH + k0 + x];
    __syncthreads();
#pragma unroll
    for (int dy = 0; dy < 32; dy += 8) Wtp[(k0 + y0 + dy) * NH + j0 + x] = tile[x][y0 + dy];
}

// ======================= encoder GRU (TMA-streamed fp32, unchanged) =======================
#define ENC_SF (16 * 768)
#define ENC_SB (ENC_SF * 4)
__global__ void __launch_bounds__(512, 1)
enc_kernel(const float* __restrict__ X, const float* __restrict__ Wih,
           const float* __restrict__ bih, const float* __restrict__ bhh) {
    extern __shared__ __align__(1024) float sm[];
    float* sW = sm;           float* sWih = sm + 24576;
    float* sh = sm + 49920;   float* sbih = sm + 50944;
    float* sbhh = sm + 51712; float* sx = sm + 52480;
    float* smb = sm + 52736;
    int tid = threadIdx.x, half = tid >> 8, tl = tid & 255;
    int b0 = blockIdx.x * 4;
    uint32_t mb0 = smem_u32(smb), mb1 = mb0 + 8, sWa = smem_u32(sW);
#pragma unroll
    for (int s = 0; s < 12; s++) {
        int fidx = tid + 512 * s;
        int j = fidx >> 3, iq = fidx & 7;
        float4 v = *reinterpret_cast<const float4*>(Wih + j * 32 + iq * 4);
        float* d = sWih + j * 33 + iq * 4;
        d[0] = v.x; d[1] = v.y; d[2] = v.z; d[3] = v.w;
    }
    for (int i = tid; i < 768; i += 512) { sbih[i] = bih[i]; sbhh[i] = bhh[i]; }
    for (int i = tid; i < 1024; i += 512) sh[i] = 0.0f;
    if (tid < 128) { int b = tid >> 5, i = tid & 31; sx[i * 4 + b] = X[((b0 + b) * TSEQ) * NP + i]; }
    if (tid == 0) { mbar_init(mb0, 1); mbar_init(mb1, 1); }
    __syncthreads();
    if (tid == 0) {
        mbar_expect(mb0, ENC_SB); bulk_cp(sWa, g_WtEnc, ENC_SB, mb0);
        mbar_expect(mb1, ENC_SB); bulk_cp(sWa + ENC_SB, g_WtEnc + ENC_SF, ENC_SB, mb1);
    }
    int ph0 = 0, ph1 = 0, sl = 0;
    const int NSL = 160;
    float bi0 = sbih[tl], bi1 = sbih[tl + 256], bi2 = sbih[tl + 512];
    float bh0 = sbhh[tl], bh1 = sbhh[tl + 256], bh2 = sbhh[tl + 512];
    for (int t = 0; t < 10; t++) {
        ull a0 = pk2(bi0 + bh0), a1 = pk2(bi1 + bh1), a2 = pk2(bh2), g2 = pk2(bi2);
        const float* sxc = sx + (t & 1) * 128;
        const float* w0p = sWih + tl * 33;
        const float* w1p = sWih + (tl + 256) * 33;
        const float* w2p = sWih + (tl + 512) * 33;
#pragma unroll
        for (int i = 0; i < 32; i++) {
            ull x2 = *reinterpret_cast<const ull*>(sxc + i * 4 + half * 2);
            FMA2(a0, pk2(w0p[i]), x2); FMA2(a1, pk2(w1p[i]), x2); FMA2(g2, pk2(w2p[i]), x2);
        }
        if (t < 9 && tid < 128) {
            int b = tid >> 5, i = tid & 31;
            sx[((t + 1) & 1) * 128 + i * 4 + b] = X[((b0 + b) * TSEQ + t + 1) * NP + i];
        }
        for (int ks = 0; ks < 16; ks++) {
            int cur = sl & 1;
            if (cur == 0) { mbar_wait(mb0, ph0); ph0 ^= 1; } else { mbar_wait(mb1, ph1); ph1 ^= 1; }
            const float* base = sW + cur * ENC_SF;
#pragma unroll
            for (int kl = 0; kl < 16; kl++) {
                const float* wr = base + kl * 768;
                ull w0 = pk2(wr[tl]), w1 = pk2(wr[tl + 256]), w2 = pk2(wr[tl + 512]);
                ull h2 = *reinterpret_cast<const ull*>(sh + (ks * 16 + kl) * 4 + half * 2);
                FMA2(a0, w0, h2); FMA2(a1, w1, h2); FMA2(a2, w2, h2);
            }
            __syncthreads();
            if (tid == 0 && sl + 2 < NSL) {
                uint32_t mb = cur ? mb1 : mb0;
                mbar_expect(mb, ENC_SB);
                bulk_cp(sWa + cur * ENC_SB, g_WtEnc + (size_t)((sl + 2) & 15) * ENC_SF, ENC_SB, mb);
            }
            sl++;
        }
        float a0x, a0y, a1x, a1y, a2x, a2y, g2x, g2y;
        upk(a0, a0x, a0y); upk(a1, a1x, a1y); upk(a2, a2x, a2y); upk(g2, g2x, g2y);
        int bs = half * 2;
        { float r = sigm(a0x), z = sigm(a1x); float n = tanhf(g2x + r * a2x);
          sh[tl * 4 + bs] = (1.0f - z) * n + z * sh[tl * 4 + bs]; }
        { float r = sigm(a0y), z = sigm(a1y); float n = tanhf(g2y + r * a2y);
          sh[tl * 4 + bs + 1] = (1.0f - z) * n + z * sh[tl * 4 + bs + 1]; }
        __syncthreads();
    }
    g_henc[(b0 + half * 2 + 0) * NH + tl] = sh[tl * 4 + half * 2 + 0];
    g_henc[(b0 + half * 2 + 1) * NH + tl] = sh[tl * 4 + half * 2 + 1];
}

// ======================= latent =======================
__global__ void __launch_bounds__(256)
lat_kernel(const float* __restrict__ eps, const float* __restrict__ mb,
           const float* __restrict__ sb_, float* __restrict__ out) {
    __shared__ float hh[NH];
    int b = blockIdx.x, tid = threadIdx.x;
    hh[tid] = g_henc[b * NH + tid];
    __syncthreads();
    float am = mb[tid], as = sb_[tid];
    const float* mT = g_mwT + tid;
    const float* sT = g_swT + tid;
#pragma unroll 8
    for (int k = 0; k < NH; k++) { float h = hh[k]; am += mT[k * NH] * h; as += sT[k * NH] * h; }
    out[126976 + b * NH + tid] = am;
    out[110592 + b * NH + tid] = as;
    g_z[b * NH + tid] = am + expf(0.5f * as) * eps[b * NH + tid];
}

// ======================= decoder GRU via mma.sync fp16 + fused input proj ====================
// SMEM layout (bytes):
//   0        .. 98304   : 2 x 48KB W chunk slots (TMA)
//   98304    .. 106752  : shi [16 b][264] fp16
//   106752   .. 115200  : slo [16 b][264] fp16
//   115200   .. 177408  : sxh [54 t][16 b][36] fp16 (dec_in, pad 36 -> conflict-free)
//   177408   .. 180480  : sbhh [768] f32
//   180480   .. 183552  : sbih [768] f32
//   183552   .. 184576  : slw [256] f32
//   184576   .. 184704  : sout [32] f32
//   184704   .. 184720  : mbarriers
#define SLOT_B   49152
#define OFF_SHI  98304
#define OFF_SLO  106752
#define OFF_SXH  115200
#define OFF_BHH  177408
#define OFF_BIH  180480
#define OFF_LW   183552
#define OFF_SOUT 184576
#define OFF_MB   184704
#define DEC_SMEM 184832

__global__ void __launch_bounds__(512, 1)
dec_mma_kernel(const float* __restrict__ X,
               const float* __restrict__ bih_all, const float* __restrict__ bhh_all,
               const float* __restrict__ lw_all, const float* __restrict__ lb_all,
               float* __restrict__ out) {
    extern __shared__ __align__(128) char smc[];
    __half* shi = (__half*)(smc + OFF_SHI);
    __half* slo = (__half*)(smc + OFF_SLO);
    __half* sxh = (__half*)(smc + OFF_SXH);
    float* sbhh = (float*)(smc + OFF_BHH);
    float* sbih = (float*)(smc + OFF_BIH);
    float* slw  = (float*)(smc + OFF_LW);
    float* sout = (float*)(smc + OFF_SOUT);
    int tid = threadIdx.x, lane = tid & 31, w = tid >> 5;
    int p = blockIdx.y, c = blockIdx.x, b0 = c * 16;
    uint32_t sb = smem_u32(smc);
    uint32_t wmb[2] = { sb + OFF_MB, sb + OFF_MB + 8 };

    for (int i = tid; i < 768; i += 512) { sbhh[i] = bhh_all[p * NG + i]; sbih[i] = bih_all[p * NG + i]; }
    if (tid < 256) slw[tid] = lw_all[p * NH + tid];
    if (tid < 32) sout[tid] = 0.0f;
    float lb = lb_all[p];
    // h images from z (fp16 hi/lo split)
    for (int i = tid; i < 4096; i += 512) {
        int b = i >> 8, j = i & 255;
        float z = g_z[(b0 + b) * NH + j];
        __half hi = __float2half(z);
        shi[b * 264 + j] = hi;
        slo[b * 264 + j] = __float2half(z - __half2float(hi));
    }
    // dec_in -> fp16 smem [t][b][k(36 pad)]
    for (int i = tid; i < TDEC * 16 * 32; i += 512) {
        int t = i >> 9, b = (i >> 5) & 15, k = i & 31;
        float v = (t == 0) ? 0.0f : X[((b0 + b) * TSEQ + 9 + t) * NP + k];
        sxh[(t * 16 + b) * 36 + k] = __float2half(v);
    }
    if (tid == 0) { mbar_init(wmb[0], 1); mbar_init(wmb[1], 1); }
    __syncthreads();
    const __half* Wf = g_Wfrag + (size_t)p * 196608;
    const __half* WihF = g_WihFrag + (size_t)p * 24576;
    if (tid == 0) {
        mbar_expect(wmb[0], SLOT_B); bulk_cp(sb, Wf, SLOT_B, wmb[0]);
        mbar_expect(wmb[1], SLOT_B); bulk_cp(sb + SLOT_B, Wf + 24576, SLOT_B, wmb[1]);
    }
    int wph[2] = {0, 0};
    int gsl = 0;
    const int NCH = TDEC * 9;            // per step: 8 Whh slices + 1 Wih chunk
    int tr0 = lane >> 2, cb0 = (lane & 3) << 1;

    for (int t = 0; t < TDEC; t++) {
        float acc[3][2][4], agi[3][2][4];
#pragma unroll
        for (int g = 0; g < 3; g++)
#pragma unroll
            for (int nt = 0; nt < 2; nt++)
#pragma unroll
                for (int q = 0; q < 4; q++) { acc[g][nt][q] = 0.0f; agi[g][nt][q] = 0.0f; }

        for (int ch = 0; ch < 9; ch++) {
            int slot = gsl & 1;
            mbar_wait(wmb[slot], wph[slot]); wph[slot] ^= 1;
            const __half* slab = (const __half*)(smc + slot * SLOT_B);
            if (ch < 8) {
                // Whh slice: 2 k-tiles x 3 gates x 2 n-tiles x 2 passes (hhi, hlo)
#pragma unroll
                for (int ktl = 0; ktl < 2; ktl++) {
                    int k0 = ch * 32 + ktl * 16 + cb0;
                    uint32_t bh[2][2], bl[2][2];
#pragma unroll
                    for (int nt = 0; nt < 2; nt++) {
                        int n = nt * 8 + tr0;
                        bh[nt][0] = *reinterpret_cast<const uint32_t*>(shi + n * 264 + k0);
                        bh[nt][1] = *reinterpret_cast<const uint32_t*>(shi + n * 264 + k0 + 8);
                        bl[nt][0] = *reinterpret_cast<const uint32_t*>(slo + n * 264 + k0);
                        bl[nt][1] = *reinterpret_cast<const uint32_t*>(slo + n * 264 + k0 + 8);
                    }
#pragma unroll
                    for (int g = 0; g < 3; g++) {
                        int mt = g * 16 + w;
                        uint4 a = *reinterpret_cast<const uint4*>(slab + ((mt * 2 + ktl) * 32 + lane) * 8);
                        hmma(acc[g][0], a, bh[0][0], bh[0][1]);
                        hmma(acc[g][1], a, bh[1][0], bh[1][1]);
                        hmma(acc[g][0], a, bl[0][0], bl[0][1]);
                        hmma(acc[g][1], a, bl[1][0], bl[1][1]);
                    }
                }
            } else {
                // Wih chunk: K=32 -> 2 k-tiles, B = dec_in[t]
#pragma unroll
                for (int ktl = 0; ktl < 2; ktl++) {
                    int k0 = ktl * 16 + cb0;
                    uint32_t bx[2][2];
#pragma unroll
                    for (int nt = 0; nt < 2; nt++) {
                        int n = nt * 8 + tr0;
                        bx[nt][0] = *reinterpret_cast<const uint32_t*>(sxh + (t * 16 + n) * 36 + k0);
                        bx[nt][1] = *reinterpret_cast<const uint32_t*>(sxh + (t * 16 + n) * 36 + k0 + 8);
                    }
#pragma unroll
                    for (int g = 0; g < 3; g++) {
                        int mt = g * 16 + w;
                        uint4 a = *reinterpret_cast<const uint4*>(slab + ((mt * 2 + ktl) * 32 + lane) * 8);
                        hmma(agi[g][0], a, bx[0][0], bx[0][1]);
                        hmma(agi[g][1], a, bx[1][0], bx[1][1]);
                    }
                }
            }
            __syncthreads();
            if (tid == 0 && gsl + 2 < NCH) {
                int nc = (gsl + 2) % 9;
                const __half* src = (nc < 8) ? (Wf + (size_t)nc * 24576) : WihF;
                mbar_expect(wmb[slot], SLOT_B);
                bulk_cp(sb + slot * SLOT_B, src, SLOT_B, wmb[slot]);
            }
            gsl++;
        }

        // ---- epilogue: gates, h update, linear head ----
        float red[2][2] = {{0.0f, 0.0f}, {0.0f, 0.0f}};
#pragma unroll
        for (int jj = 0; jj < 2; jj++) {
            int j = w * 16 + tr0 + jj * 8;
            float br = sbhh[j], bz = sbhh[256 + j], bn = sbhh[512 + j];
            float ir = sbih[j], iz = sbih[256 + j], in_ = sbih[512 + j];
            float lwj = slw[j];
#pragma unroll
            for (int nt = 0; nt < 2; nt++) {
#pragma unroll
                for (int cs = 0; cs < 2; cs++) {
                    int ci = jj * 2 + cs;
                    int b = nt * 8 + cb0 + cs;
                    float hold = __half2float(shi[b * 264 + j]) + __half2float(slo[b * 264 + j]);
                    float r = sigm(agi[0][nt][ci] + ir + br + acc[0][nt][ci]);
                    float z = sigm(agi[1][nt][ci] + iz + bz + acc[1][nt][ci]);
                    float n = tanhf(agi[2][nt][ci] + in_ + r * (bn + acc[2][nt][ci]));
                    float hv = (1.0f - z) * n + z * hold;
                    __half hh = __float2half(hv);
                    shi[b * 264 + j] = hh;
                    slo[b * 264 + j] = __float2half(hv - __half2float(hh));
                    red[nt][cs] += lwj * hv;
                }
            }
        }
#pragma unroll
        for (int nt = 0; nt < 2; nt++)
#pragma unroll
            for (int cs = 0; cs < 2; cs++) {
                float v = red[nt][cs];
                v += __shfl_xor_sync(0xffffffffu, v, 4);
                v += __shfl_xor_sync(0xffffffffu, v, 8);
                v += __shfl_xor_sync(0xffffffffu, v, 16);
                if (tr0 == 0) atomicAdd(sout + (t & 1) * 16 + nt * 8 + cb0 + cs, v);
            }
        __syncthreads();
        if (tid < 16) {
            out[((size_t)p * NB + b0 + tid) * TDEC + t] = sout[(t & 1) * 16 + tid] + lb;
            sout[(t & 1) * 16 + tid] = 0.0f;   // reused at t+2; ordered by t+1's barriers
        }
    }
}

// ======================= launcher =======================
extern "C" void kernel_launch(void* const* d_in, const int* in_sizes, int n_in,
                              void* d_out, int out_size) {
    const float* X       = (const float*)d_in[0];
    const float* eps     = (const float*)d_in[1];
    const float* Wih_enc = (const float*)d_in[2];
    const float* Whh_enc = (const float*)d_in[3];
    const float* bih_enc = (const float*)d_in[4];
    const float* bhh_enc = (const float*)d_in[5];
    const float* mw      = (const float*)d_in[6];
    const float* mb      = (const float*)d_in[7];
    const float* sw      = (const float*)d_in[8];
    const float* sb      = (const float*)d_in[9];
    const float* Wih_dec = (const float*)d_in[10];
    const float* Whh_dec = (const float*)d_in[11];
    const float* bih_dec = (const float*)d_in[12];
    const float* bhh_dec = (const float*)d_in[13];
    const float* lw      = (const float*)d_in[14];
    const float* lbv     = (const float*)d_in[15];
    float* out = (float*)d_out;

    int smem_enc = 52740 * 4;
    cudaFuncSetAttribute(enc_kernel,     cudaFuncAttributeMaxDynamicSharedMemorySize, smem_enc);
    cudaFuncSetAttribute(dec_mma_kernel, cudaFuncAttributeMaxDynamicSharedMemorySize, DEC_SMEM);

    wprep_kernel<<<dim3(96, 32), 256>>>(Whh_dec);
    wprep_ih_kernel<<<dim3(12, 32), 256>>>(Wih_dec);
    tr_enc_kernel<<<dim3(8, 24), dim3(32, 8)>>>(Whh_enc);
    trf_kernel<<<dim3(8, 8, 2), dim3(32, 8)>>>(mw, sw);
    enc_kernel<<<16, 512, smem_enc>>>(X, Wih_enc, bih_enc, bhh_enc);
    lat_kernel<<<NB, 256>>>(eps, mb, sb, out);
    dec_mma_kernel<<<dim3(4, NP), 512, DEC_SMEM>>>(X, bih_dec, bhh_dec, lw, lbv, out);
}